// round 6
// baseline (speedup 1.0000x reference)
#include <cuda_runtime.h>
#include <cuda_bf16.h>
#include <cstdint>

#define NH   12
#define SLEN 4096
#define HD   64
#define DIM  768
#define GRD  64
#define LOG2E 1.4426950408889634f

// ---------------- scratch ----------------------------------------------------
__device__ float g_relh[NH * SLEN * GRD];
__device__ float g_relw[NH * SLEN * GRD];

// split-bf16 operands (hi + lo ~ fp32)
__device__ __nv_bfloat16 g_Qh[NH * SLEN * HD];   // pre-scaled by 0.125
__device__ __nv_bfloat16 g_Ql[NH * SLEN * HD];
__device__ __nv_bfloat16 g_Kh[NH * SLEN * HD];
__device__ __nv_bfloat16 g_Kl[NH * SLEN * HD];
__device__ __nv_bfloat16 g_Vth[NH * HD * SLEN];  // transposed: [head][c][s]
__device__ __nv_bfloat16 g_Vtl[NH * HD * SLEN];

__device__ __nv_bfloat16 g_Xh[SLEN * DIM];       // x split
__device__ __nv_bfloat16 g_Xl[SLEN * DIM];
__device__ __nv_bfloat16 g_W1h[3 * DIM * DIM];   // qkv_w split
__device__ __nv_bfloat16 g_W1l[3 * DIM * DIM];
__device__ __nv_bfloat16 g_W2h[DIM * DIM];       // proj_w split
__device__ __nv_bfloat16 g_W2l[DIM * DIM];
__device__ __nv_bfloat16 g_aoh[SLEN * DIM];      // attention out split
__device__ __nv_bfloat16 g_aol[SLEN * DIM];

// ---------------- helpers -----------------------------------------------------
__device__ __forceinline__ uint32_t smem_u32(const void* p) {
    uint32_t a;
    asm("{ .reg .u64 t; cvta.to.shared.u64 t, %1; cvt.u32.u64 %0, t; }" : "=r"(a) : "l"(p));
    return a;
}

#define CP_ASYNC16(sm, gp) \
    asm volatile("cp.async.cg.shared.global [%0], [%1], 16;" :: "r"(sm), "l"(gp))
#define CP_COMMIT()  asm volatile("cp.async.commit_group;")
#define CP_WAIT1()   asm volatile("cp.async.wait_group 1;")
#define CP_WAIT0()   asm volatile("cp.async.wait_group 0;")

#define LDSM_X2(r0, r1, addr) \
    asm volatile("ldmatrix.sync.aligned.m8n8.x2.shared.b16 {%0,%1}, [%2];" \
                 : "=r"(r0), "=r"(r1) : "r"(addr))
#define LDSM_X4(r0, r1, r2, r3, addr) \
    asm volatile("ldmatrix.sync.aligned.m8n8.x4.shared.b16 {%0,%1,%2,%3}, [%4];" \
                 : "=r"(r0), "=r"(r1), "=r"(r2), "=r"(r3) : "r"(addr))

#define MMA16816(d, a, b0, b1) \
    asm volatile("mma.sync.aligned.m16n8k16.row.col.f32.bf16.bf16.f32 " \
        "{%0,%1,%2,%3}, {%4,%5,%6,%7}, {%8,%9}, {%0,%1,%2,%3};" \
        : "+f"((d)[0]), "+f"((d)[1]), "+f"((d)[2]), "+f"((d)[3]) \
        : "r"((a)[0]), "r"((a)[1]), "r"((a)[2]), "r"((a)[3]), "r"(b0), "r"(b1))

__device__ __forceinline__ void split2(float x, float y, uint32_t& hi, uint32_t& lo) {
    __nv_bfloat162 h = __float22bfloat162_rn(make_float2(x, y));
    float rx = x - __low2float(h);
    float ry = y - __high2float(h);
    __nv_bfloat162 l = __float22bfloat162_rn(make_float2(rx, ry));
    hi = *reinterpret_cast<uint32_t*>(&h);
    lo = *reinterpret_cast<uint32_t*>(&l);
}

// ---------------- input conversion (x, qkv_w, proj_w -> split bf16) ----------
#define NX (SLEN * DIM)
#define NW1 (3 * DIM * DIM)
#define NW2 (DIM * DIM)
__global__ void convert_in(const float* __restrict__ x,
                           const float* __restrict__ w1,
                           const float* __restrict__ w2)
{
    for (size_t i = (size_t)blockIdx.x * 256 + threadIdx.x;
         i < (size_t)(NX + NW1 + NW2); i += (size_t)gridDim.x * 256) {
        float v; __nv_bfloat16 *dh, *dl; size_t j;
        if (i < NX)            { j = i;             v = x[j];  dh = g_Xh;  dl = g_Xl;  }
        else if (i < NX + NW1) { j = i - NX;        v = w1[j]; dh = g_W1h; dl = g_W1l; }
        else                   { j = i - NX - NW1;  v = w2[j]; dh = g_W2h; dl = g_W2l; }
        __nv_bfloat16 h = __float2bfloat16(v);
        dh[j] = h;
        dl[j] = __float2bfloat16(v - __bfloat162float(h));
    }
}

// ---------------- split-bf16 tensor GEMM (proven round 4) --------------------
#define TG 80
#define G_AH 0
#define G_AL (128 * TG)
#define G_BH (2 * 128 * TG)
#define G_BL (2 * 128 * TG + 64 * TG)
#define G_STG (2 * 128 * TG + 2 * 64 * TG)
#define SMEM_GEMM (2 * G_STG)

template <int MODE>
__global__ void __launch_bounds__(256) gemm_bf16(
    const __nv_bfloat16* __restrict__ Agh, const __nv_bfloat16* __restrict__ Agl,
    const __nv_bfloat16* __restrict__ Bgh, const __nv_bfloat16* __restrict__ Bgl,
    const float* __restrict__ bias, float* __restrict__ out)
{
    extern __shared__ char smem[];
    const uint32_t sb = smem_u32(smem);
    const int tid  = threadIdx.x;
    const int lane = tid & 31;
    const int warp = tid >> 5;
    const int g    = lane >> 2;
    const int tm   = lane & 3;
    const int bm   = blockIdx.y * 128;
    const int bn   = blockIdx.x * 64;
    const int qr   = warp * 16;

    auto load_tile = [&](int buf, int kt) {
        const uint32_t st = sb + buf * G_STG;
        const int k0 = kt * 32;
#pragma unroll
        for (int rep = 0; rep < 6; rep++) {
            int c = tid + rep * 256;
            if (c < 512) {
                int row = c >> 2, off = c & 3;
                CP_ASYNC16(st + G_AH + row * TG + off * 16,
                           Agh + (size_t)(bm + row) * DIM + k0 + off * 8);
            } else if (c < 1024) {
                int cc = c - 512, row = cc >> 2, off = cc & 3;
                CP_ASYNC16(st + G_AL + row * TG + off * 16,
                           Agl + (size_t)(bm + row) * DIM + k0 + off * 8);
            } else if (c < 1280) {
                int cc = c - 1024, row = cc >> 2, off = cc & 3;
                CP_ASYNC16(st + G_BH + row * TG + off * 16,
                           Bgh + (size_t)(bn + row) * DIM + k0 + off * 8);
            } else {
                int cc = c - 1280, row = cc >> 2, off = cc & 3;
                CP_ASYNC16(st + G_BL + row * TG + off * 16,
                           Bgl + (size_t)(bn + row) * DIM + k0 + off * 8);
            }
        }
    };

    const uint32_t arow = (uint32_t)((lane & 15) * TG + (lane >> 4) * 16) + qr * TG;
    const uint32_t brow = (uint32_t)((lane & 7) * TG + (((lane & 15) >> 3) << 4));

    float sc[8][4];
#pragma unroll
    for (int nb = 0; nb < 8; nb++)
#pragma unroll
        for (int j = 0; j < 4; j++) sc[nb][j] = 0.0f;

    load_tile(0, 0);
    CP_COMMIT();

    for (int kt = 0; kt < 24; kt++) {
        if (kt < 23) { load_tile((kt + 1) & 1, kt + 1); CP_COMMIT(); CP_WAIT1(); }
        else         { CP_WAIT0(); }
        __syncthreads();

        const uint32_t st = sb + (kt & 1) * G_STG;
#pragma unroll
        for (int ks = 0; ks < 2; ks++) {
            uint32_t ah[4], al[4];
            LDSM_X4(ah[0], ah[1], ah[2], ah[3], st + G_AH + arow + ks * 32);
            LDSM_X4(al[0], al[1], al[2], al[3], st + G_AL + arow + ks * 32);
#pragma unroll
            for (int nb = 0; nb < 8; nb++) {
                uint32_t bh0, bh1, bl0, bl1;
                LDSM_X2(bh0, bh1, st + G_BH + brow + nb * (8 * TG) + ks * 32);
                LDSM_X2(bl0, bl1, st + G_BL + brow + nb * (8 * TG) + ks * 32);
                MMA16816(sc[nb], ah, bh0, bh1);
                MMA16816(sc[nb], ah, bl0, bl1);
                MMA16816(sc[nb], al, bh0, bh1);
            }
        }
        __syncthreads();
    }

    const int r0 = bm + qr + g, r1 = r0 + 8;
    if (MODE == 1) {
#pragma unroll
        for (int nb = 0; nb < 8; nb++) {
            const int jj = bn + nb * 8 + tm * 2;
            const float b0 = bias[jj], b1 = bias[jj + 1];
            *(float2*)&out[(size_t)r0 * DIM + jj] = make_float2(sc[nb][0] + b0, sc[nb][1] + b1);
            *(float2*)&out[(size_t)r1 * DIM + jj] = make_float2(sc[nb][2] + b0, sc[nb][3] + b1);
        }
    } else {
        const int which = bn / DIM;
        const int head  = (bn % DIM) >> 6;
#pragma unroll
        for (int nb = 0; nb < 8; nb++) {
            const int jj  = bn + nb * 8 + tm * 2;
            const int col = nb * 8 + tm * 2;
            const float b0 = bias[jj], b1 = bias[jj + 1];
            float v00 = sc[nb][0] + b0, v01 = sc[nb][1] + b1;
            float v10 = sc[nb][2] + b0, v11 = sc[nb][3] + b1;
            if (which == 0) {
                uint32_t h, l;
                split2(v00 * 0.125f, v01 * 0.125f, h, l);
                *(uint32_t*)&g_Qh[((size_t)head * SLEN + r0) * HD + col] = h;
                *(uint32_t*)&g_Ql[((size_t)head * SLEN + r0) * HD + col] = l;
                split2(v10 * 0.125f, v11 * 0.125f, h, l);
                *(uint32_t*)&g_Qh[((size_t)head * SLEN + r1) * HD + col] = h;
                *(uint32_t*)&g_Ql[((size_t)head * SLEN + r1) * HD + col] = l;
            } else if (which == 1) {
                uint32_t h, l;
                split2(v00, v01, h, l);
                *(uint32_t*)&g_Kh[((size_t)head * SLEN + r0) * HD + col] = h;
                *(uint32_t*)&g_Kl[((size_t)head * SLEN + r0) * HD + col] = l;
                split2(v10, v11, h, l);
                *(uint32_t*)&g_Kh[((size_t)head * SLEN + r1) * HD + col] = h;
                *(uint32_t*)&g_Kl[((size_t)head * SLEN + r1) * HD + col] = l;
            } else {
                float vv[4] = {v00, v01, v10, v11};
                int rr[4] = {r0, r0, r1, r1};
                int cc[4] = {col, col + 1, col, col + 1};
#pragma unroll
                for (int e = 0; e < 4; e++) {
                    __nv_bfloat16 h = __float2bfloat16(vv[e]);
                    size_t ti = ((size_t)head * HD + cc[e]) * SLEN + rr[e];
                    g_Vth[ti] = h;
                    g_Vtl[ti] = __float2bfloat16(vv[e] - __bfloat162float(h));
                }
            }
        }
    }
}

// ---------------- rel-pos bias (merged h/w; Q from split) --------------------
#define REL_SM_FLOATS (64 * 68 + 127 * 65)
__global__ void rel_kernel(const float* __restrict__ rph,
                           const float* __restrict__ rpw)
{
    extern __shared__ float sm[];
    float* Qs = sm;
    float* R  = sm + 64 * 68;
    const int qh = blockIdx.x, head = blockIdx.y;
    const int isW = blockIdx.z;
    const float* relpos = isW ? rpw : rph;
    const int tid = threadIdx.x;
    const int tx = tid & 15, ty = tid >> 4;

    const __nv_bfloat16* Qhg = &g_Qh[((size_t)head * SLEN + qh * GRD) * HD];
    const __nv_bfloat16* Qlg = &g_Ql[((size_t)head * SLEN + qh * GRD) * HD];
    for (int t = tid; t < 4096; t += 256) {
        int c = t & 63, qw = t >> 6;
        Qs[c * 68 + qw] = 8.0f * (__bfloat162float(Qhg[(size_t)qw * HD + c]) +
                                  __bfloat162float(Qlg[(size_t)qw * HD + c]));
    }

    if (!isW) {
        for (int t = tid; t < 4096; t += 256) {
            int c = t & 63, kh = t >> 6;
            R[c * 68 + kh] = relpos[(qh - kh + 63) * 64 + c];
        }
        __syncthreads();
        float acc[4][4] = {};
#pragma unroll 4
        for (int c = 0; c < 64; c++) {
            float4 a = *(const float4*)&Qs[c * 68 + (ty << 2)];
            float4 b = *(const float4*)&R[c * 68 + (tx << 2)];
            float av[4] = {a.x, a.y, a.z, a.w};
            float bv[4] = {b.x, b.y, b.z, b.w};
#pragma unroll
            for (int i = 0; i < 4; i++)
#pragma unroll
                for (int j = 0; j < 4; j++) acc[i][j] += av[i] * bv[j];
        }
#pragma unroll
        for (int i = 0; i < 4; i++)
#pragma unroll
            for (int j = 0; j < 4; j++) {
                int qw = (ty << 2) + i, kh = (tx << 2) + j;
                g_relh[((size_t)head * SLEN + qh * 64 + qw) * 64 + kh] = acc[i][j];
            }
    } else {
        for (int t = tid; t < 127 * 64; t += 256) {
            int c = t & 63, rr = t >> 6;
            R[rr * 65 + c] = relpos[rr * 64 + c];
        }
        __syncthreads();
        float acc[4][4] = {};
        const int qwb = ty << 2, kwb = tx << 2;
        for (int c = 0; c < 64; c++) {
            float4 a = *(const float4*)&Qs[c * 68 + qwb];
            float av[4] = {a.x, a.y, a.z, a.w};
#pragma unroll
            for (int i = 0; i < 4; i++)
#pragma unroll
                for (int j = 0; j < 4; j++)
                    acc[i][j] += av[i] * R[(qwb + i - kwb - j + 63) * 65 + c];
        }
#pragma unroll
        for (int i = 0; i < 4; i++)
#pragma unroll
            for (int j = 0; j < 4; j++) {
                int qw = qwb + i, kw = kwb + j;
                g_relw[((size_t)head * SLEN + qh * 64 + qw) * 64 + kw] = acc[i][j];
            }
    }
}

// ---------------- mma.sync flash attention, software-pipelined ---------------
// 128 threads = 4 warps; q-tile 64; key-tile 64. K-ring and V-ring (2 stages
// each) skewed by one tile: iteration kt computes softmax(kt)+PV(kt) AND the
// raw S-MMAs of tile kt+1, so tensor work covers the ALU/MUFU phase.
#define TROW     144
#define K_ST(b)  ((b) * 18432)                 // Kh then Kl (9216 each)
#define V_ST(b)  (36864 + (b) * 18432)         // Vh then Vl
#define RH_OFF   73728
#define RW_OFF   (RH_OFF + 64 * 66 * 4)
#define SMEM_ATTN (RW_OFF + 64 * 66 * 4)       // 107520

__global__ void __launch_bounds__(128, 2) attn_mma_kernel()
{
    extern __shared__ char smem[];
    const uint32_t sb = smem_u32(smem);
    const int tid  = threadIdx.x;
    const int lane = tid & 31;
    const int warp = tid >> 5;
    const int g    = lane >> 2;
    const int tm   = lane & 3;
    const int head = blockIdx.y;
    const int q0   = blockIdx.x * 64;
    const int qr   = warp * 16;

    float* rhS = (float*)(smem + RH_OFF);
    float* rwS = (float*)(smem + RW_OFF);

    // rel tables (pre-scaled by log2(e) so softmax runs in base-2)
    for (int t = tid; t < 4096; t += 128) {
        int row = t >> 6, k = t & 63;
        rhS[row * 66 + k] = LOG2E * g_relh[((size_t)head * SLEN + q0 + row) * 64 + k];
        rwS[row * 66 + k] = LOG2E * g_relw[((size_t)head * SLEN + q0 + row) * 64 + k];
    }

    uint32_t qhf[4][4], qlf[4][4];
    {
        const uint32_t* q0h = (const uint32_t*)(g_Qh + ((size_t)head * SLEN + q0 + qr + g) * HD);
        const uint32_t* q1h = (const uint32_t*)(g_Qh + ((size_t)head * SLEN + q0 + qr + g + 8) * HD);
        const uint32_t* q0l = (const uint32_t*)(g_Ql + ((size_t)head * SLEN + q0 + qr + g) * HD);
        const uint32_t* q1l = (const uint32_t*)(g_Ql + ((size_t)head * SLEN + q0 + qr + g + 8) * HD);
#pragma unroll
        for (int ks = 0; ks < 4; ks++) {
            qhf[ks][0] = q0h[ks * 8 + tm];     qhf[ks][1] = q1h[ks * 8 + tm];
            qhf[ks][2] = q0h[ks * 8 + tm + 4]; qhf[ks][3] = q1h[ks * 8 + tm + 4];
            qlf[ks][0] = q0l[ks * 8 + tm];     qlf[ks][1] = q1l[ks * 8 + tm];
            qlf[ks][2] = q0l[ks * 8 + tm + 4]; qlf[ks][3] = q1l[ks * 8 + tm + 4];
        }
    }

    const uint32_t b4off = (uint32_t)((lane & 7) * TROW + ((lane >> 3) & 1) * 16 +
                                      ((lane >> 4) & 1) * (8 * TROW));

    const char* KhG = (const char*)(g_Kh + (size_t)head * SLEN * HD);
    const char* KlG = (const char*)(g_Kl + (size_t)head * SLEN * HD);
    const char* VhG = (const char*)(g_Vth + (size_t)head * HD * SLEN);
    const char* VlG = (const char*)(g_Vtl + (size_t)head * HD * SLEN);

    auto loadK = [&](int t) {       // K(t) -> K stage t&1
        const uint32_t st = sb + K_ST(t & 1);
#pragma unroll
        for (int rep = 0; rep < 4; rep++) {
            int c = tid + rep * 128;
            int row = c >> 3, off = c & 7;
            CP_ASYNC16(st + row * TROW + off * 16,
                       KhG + (size_t)(t * 64 + row) * 128 + off * 16);
            CP_ASYNC16(st + 9216 + row * TROW + off * 16,
                       KlG + (size_t)(t * 64 + row) * 128 + off * 16);
        }
    };
    auto loadV = [&](int t) {       // V(t) -> V stage t&1
        const uint32_t st = sb + V_ST(t & 1);
#pragma unroll
        for (int rep = 0; rep < 4; rep++) {
            int c = tid + rep * 128;
            int row = c >> 3, off = c & 7;
            CP_ASYNC16(st + row * TROW + off * 16,
                       VhG + (size_t)row * 8192 + (size_t)t * 128 + off * 16);
            CP_ASYNC16(st + 9216 + row * TROW + off * 16,
                       VlG + (size_t)row * 8192 + (size_t)t * 128 + off * 16);
        }
    };

    // raw S-MMAs of one key tile from K stage base into s[8][4]
    auto computeS = [&](float s[8][4], uint32_t kst) {
        const uint32_t kh0 = kst + b4off;
        const uint32_t kl0 = kst + 9216 + b4off;
#pragma unroll
        for (int ks = 0; ks < 4; ks++) {
#pragma unroll
            for (int nb2 = 0; nb2 < 4; nb2++) {
                uint32_t bh0, bh1, bh2, bh3, bl0, bl1, bl2, bl3;
                LDSM_X4(bh0, bh1, bh2, bh3, kh0 + nb2 * (16 * TROW) + ks * 32);
                LDSM_X4(bl0, bl1, bl2, bl3, kl0 + nb2 * (16 * TROW) + ks * 32);
                MMA16816(s[2 * nb2], qhf[ks], bh0, bh1);
                MMA16816(s[2 * nb2], qhf[ks], bl0, bl1);
                MMA16816(s[2 * nb2], qlf[ks], bh0, bh1);
                MMA16816(s[2 * nb2 + 1], qhf[ks], bh2, bh3);
                MMA16816(s[2 * nb2 + 1], qhf[ks], bl2, bl3);
                MMA16816(s[2 * nb2 + 1], qlf[ks], bh2, bh3);
            }
        }
    };

    float o[8][4];
#pragma unroll
    for (int cb = 0; cb < 8; cb++)
#pragma unroll
        for (int j = 0; j < 4; j++) o[cb][j] = 0.0f;
    float m0 = -1e30f, m1 = -1e30f, l0 = 0.0f, l1 = 0.0f;

    // ---- prologue: K(0), K(1), V(0); then S(0) ----
    loadK(0); loadK(1); loadV(0);
    CP_COMMIT();
    CP_WAIT0();
    __syncthreads();

    float sn[8][4];
#pragma unroll
    for (int nb = 0; nb < 8; nb++)
#pragma unroll
        for (int j = 0; j < 4; j++) sn[nb][j] = 0.0f;
    computeS(sn, sb + K_ST(0));

    for (int kt = 0; kt < 64; kt++) {
        CP_WAIT0();
        __syncthreads();   // all loads visible; all warps done with prev compute

        // issue next loads (targets consumed a full phase ago)
        if (kt + 2 < 64) loadK(kt + 2);
        if (kt + 1 < 64) loadV(kt + 1);
        CP_COMMIT();

        // take S(kt), start S(kt+1) immediately (covers the ALU phase below)
        float sc[8][4];
#pragma unroll
        for (int nb = 0; nb < 8; nb++)
#pragma unroll
            for (int j = 0; j < 4; j++) { sc[nb][j] = sn[nb][j]; sn[nb][j] = 0.0f; }
        if (kt < 63) computeS(sn, sb + K_ST((kt + 1) & 1));

        // ---- bias + online softmax (base-2) ----
        const int r0 = qr + g, r1 = r0 + 8;
        const float rh0 = rhS[r0 * 66 + kt];
        const float rh1 = rhS[r1 * 66 + kt];
        float mt0 = -1e30f, mt1 = -1e30f;
#pragma unroll
        for (int nb = 0; nb < 8; nb++) {
            float2 w0 = *(const float2*)&rwS[r0 * 66 + nb * 8 + tm * 2];
            float2 w1 = *(const float2*)&rwS[r1 * 66 + nb * 8 + tm * 2];
            sc[nb][0] = fmaf(sc[nb][0], LOG2E, rh0 + w0.x);
            sc[nb][1] = fmaf(sc[nb][1], LOG2E, rh0 + w0.y);
            sc[nb][2] = fmaf(sc[nb][2], LOG2E, rh1 + w1.x);
            sc[nb][3] = fmaf(sc[nb][3], LOG2E, rh1 + w1.y);
            mt0 = fmaxf(mt0, fmaxf(sc[nb][0], sc[nb][1]));
            mt1 = fmaxf(mt1, fmaxf(sc[nb][2], sc[nb][3]));
        }
        mt0 = fmaxf(mt0, __shfl_xor_sync(0xffffffffu, mt0, 1));
        mt0 = fmaxf(mt0, __shfl_xor_sync(0xffffffffu, mt0, 2));
        mt1 = fmaxf(mt1, __shfl_xor_sync(0xffffffffu, mt1, 1));
        mt1 = fmaxf(mt1, __shfl_xor_sync(0xffffffffu, mt1, 2));

        const float mn0 = fmaxf(m0, mt0);
        const float mn1 = fmaxf(m1, mt1);
        const float a0 = exp2f(m0 - mn0);
        const float a1 = exp2f(m1 - mn1);
        m0 = mn0; m1 = mn1;

        float s0 = 0.0f, s1 = 0.0f;
#pragma unroll
        for (int nb = 0; nb < 8; nb++) {
            sc[nb][0] = exp2f(sc[nb][0] - mn0);
            sc[nb][1] = exp2f(sc[nb][1] - mn0);
            sc[nb][2] = exp2f(sc[nb][2] - mn1);
            sc[nb][3] = exp2f(sc[nb][3] - mn1);
            s0 += sc[nb][0] + sc[nb][1];
            s1 += sc[nb][2] + sc[nb][3];
        }
        s0 += __shfl_xor_sync(0xffffffffu, s0, 1);
        s0 += __shfl_xor_sync(0xffffffffu, s0, 2);
        s1 += __shfl_xor_sync(0xffffffffu, s1, 1);
        s1 += __shfl_xor_sync(0xffffffffu, s1, 2);
        l0 = l0 * a0 + s0;
        l1 = l1 * a1 + s1;

#pragma unroll
        for (int cb = 0; cb < 8; cb++) {
            o[cb][0] *= a0; o[cb][1] *= a0;
            o[cb][2] *= a1; o[cb][3] *= a1;
        }

        // ---- O += Ph Vh + Ph Vl + Pl Vh ----
        const uint32_t vst = sb + V_ST(kt & 1);
        const uint32_t vh0 = vst + b4off;
        const uint32_t vl0 = vst + 9216 + b4off;
#pragma unroll
        for (int kb = 0; kb < 4; kb++) {
            uint32_t ph[4], pl[4];
            split2(sc[2 * kb][0],     sc[2 * kb][1],     ph[0], pl[0]);
            split2(sc[2 * kb][2],     sc[2 * kb][3],     ph[1], pl[1]);
            split2(sc[2 * kb + 1][0], sc[2 * kb + 1][1], ph[2], pl[2]);
            split2(sc[2 * kb + 1][2], sc[2 * kb + 1][3], ph[3], pl[3]);
#pragma unroll
            for (int cb2 = 0; cb2 < 4; cb2++) {
                uint32_t bh0, bh1, bh2, bh3, bl0, bl1, bl2, bl3;
                LDSM_X4(bh0, bh1, bh2, bh3, vh0 + cb2 * (16 * TROW) + kb * 32);
                LDSM_X4(bl0, bl1, bl2, bl3, vl0 + cb2 * (16 * TROW) + kb * 32);
                MMA16816(o[2 * cb2], ph, bh0, bh1);
                MMA16816(o[2 * cb2], ph, bl0, bl1);
                MMA16816(o[2 * cb2], pl, bh0, bh1);
                MMA16816(o[2 * cb2 + 1], ph, bh2, bh3);
                MMA16816(o[2 * cb2 + 1], ph, bl2, bl3);
                MMA16816(o[2 * cb2 + 1], pl, bh2, bh3);
            }
        }
    }

    // ---- normalize + write split-bf16 attention output ----
    const float i0 = 1.0f / l0;
    const float i1 = 1.0f / l1;
    const size_t o0 = (size_t)(q0 + qr + g) * DIM + head * HD;
    const size_t o1 = (size_t)(q0 + qr + g + 8) * DIM + head * HD;
#pragma unroll
    for (int cb = 0; cb < 8; cb++) {
        const int col = cb * 8 + tm * 2;
        uint32_t h, l;
        split2(o[cb][0] * i0, o[cb][1] * i0, h, l);
        *(uint32_t*)&g_aoh[o0 + col] = h;
        *(uint32_t*)&g_aol[o0 + col] = l;
        split2(o[cb][2] * i1, o[cb][3] * i1, h, l);
        *(uint32_t*)&g_aoh[o1 + col] = h;
        *(uint32_t*)&g_aol[o1 + col] = l;
    }
}

// ---------------- launch ------------------------------------------------------
extern "C" void kernel_launch(void* const* d_in, const int* in_sizes, int n_in,
                              void* d_out, int out_size)
{
    const float* x      = (const float*)d_in[0];
    const float* qkv_w  = (const float*)d_in[1];
    const float* qkv_b  = (const float*)d_in[2];
    const float* proj_w = (const float*)d_in[3];
    const float* proj_b = (const float*)d_in[4];
    const float* rph    = (const float*)d_in[5];
    const float* rpw    = (const float*)d_in[6];
    float* out = (float*)d_out;

    const int rel_sm = REL_SM_FLOATS * (int)sizeof(float);
    cudaFuncSetAttribute(rel_kernel, cudaFuncAttributeMaxDynamicSharedMemorySize, rel_sm);
    cudaFuncSetAttribute(attn_mma_kernel, cudaFuncAttributeMaxDynamicSharedMemorySize, SMEM_ATTN);
    cudaFuncSetAttribute(gemm_bf16<0>, cudaFuncAttributeMaxDynamicSharedMemorySize, SMEM_GEMM);
    cudaFuncSetAttribute(gemm_bf16<1>, cudaFuncAttributeMaxDynamicSharedMemorySize, SMEM_GEMM);

    __nv_bfloat16 *Xh, *Xl, *W1h, *W1l, *W2h, *W2l, *AOh, *AOl;
    cudaGetSymbolAddress((void**)&Xh,  g_Xh);
    cudaGetSymbolAddress((void**)&Xl,  g_Xl);
    cudaGetSymbolAddress((void**)&W1h, g_W1h);
    cudaGetSymbolAddress((void**)&W1l, g_W1l);
    cudaGetSymbolAddress((void**)&W2h, g_W2h);
    cudaGetSymbolAddress((void**)&W2l, g_W2l);
    cudaGetSymbolAddress((void**)&AOh, g_aoh);
    cudaGetSymbolAddress((void**)&AOl, g_aol);

    // 1) split inputs to bf16 hi/lo
    convert_in<<<2048, 256>>>(x, qkv_w, proj_w);

    // 2) qkv GEMM (tensor) -> split Q/K/V (Q pre-scaled, V transposed)
    gemm_bf16<0><<<dim3(3 * DIM / 64, SLEN / 128), 256, SMEM_GEMM>>>(
        Xh, Xl, W1h, W1l, qkv_b, nullptr);

    // 3) rel-pos bias tables (h and w fused in one launch)
    rel_kernel<<<dim3(GRD, NH, 2), 256, rel_sm>>>(rph, rpw);

    // 4) software-pipelined mma.sync flash attention
    attn_mma_kernel<<<dim3(SLEN / 64, NH), 128, SMEM_ATTN>>>();

    // 5) proj GEMM (tensor) -> out
    gemm_bf16<1><<<dim3(DIM / 64, SLEN / 128), 256, SMEM_GEMM>>>(
        AOh, AOl, W2h, W2l, proj_b, out);
}

// round 7
// speedup vs baseline: 1.0304x; 1.0304x over previous
#include <cuda_runtime.h>
#include <cuda_bf16.h>
#include <cstdint>

#define NH   12
#define SLEN 4096
#define HD   64
#define DIM  768
#define GRD  64
#define LOG2E 1.4426950408889634f

// ---------------- scratch ----------------------------------------------------
__device__ float g_relh[NH * SLEN * GRD];
__device__ float g_relw[NH * SLEN * GRD];

// split-bf16 operands (hi + lo ~ fp32)
__device__ __nv_bfloat16 g_Qh[NH * SLEN * HD];   // pre-scaled by 0.125
__device__ __nv_bfloat16 g_Ql[NH * SLEN * HD];
__device__ __nv_bfloat16 g_Kh[NH * SLEN * HD];
__device__ __nv_bfloat16 g_Kl[NH * SLEN * HD];
__device__ __nv_bfloat16 g_Vth[NH * HD * SLEN];  // transposed: [head][c][s]
__device__ __nv_bfloat16 g_Vtl[NH * HD * SLEN];

__device__ __nv_bfloat16 g_Xh[SLEN * DIM];       // x split
__device__ __nv_bfloat16 g_Xl[SLEN * DIM];
__device__ __nv_bfloat16 g_W1h[3 * DIM * DIM];   // qkv_w split
__device__ __nv_bfloat16 g_W1l[3 * DIM * DIM];
__device__ __nv_bfloat16 g_W2h[DIM * DIM];       // proj_w split
__device__ __nv_bfloat16 g_W2l[DIM * DIM];
__device__ __nv_bfloat16 g_aoh[SLEN * DIM];      // attention out split
__device__ __nv_bfloat16 g_aol[SLEN * DIM];

// ---------------- helpers -----------------------------------------------------
__device__ __forceinline__ uint32_t smem_u32(const void* p) {
    uint32_t a;
    asm("{ .reg .u64 t; cvta.to.shared.u64 t, %1; cvt.u32.u64 %0, t; }" : "=r"(a) : "l"(p));
    return a;
}

#define CP_ASYNC16(sm, gp) \
    asm volatile("cp.async.cg.shared.global [%0], [%1], 16;" :: "r"(sm), "l"(gp))
#define CP_COMMIT()  asm volatile("cp.async.commit_group;")
#define CP_WAIT1()   asm volatile("cp.async.wait_group 1;")
#define CP_WAIT0()   asm volatile("cp.async.wait_group 0;")

#define LDSM_X2(r0, r1, addr) \
    asm volatile("ldmatrix.sync.aligned.m8n8.x2.shared.b16 {%0,%1}, [%2];" \
                 : "=r"(r0), "=r"(r1) : "r"(addr))
#define LDSM_X4(r0, r1, r2, r3, addr) \
    asm volatile("ldmatrix.sync.aligned.m8n8.x4.shared.b16 {%0,%1,%2,%3}, [%4];" \
                 : "=r"(r0), "=r"(r1), "=r"(r2), "=r"(r3) : "r"(addr))

#define MMA16816(d, a, b0, b1) \
    asm volatile("mma.sync.aligned.m16n8k16.row.col.f32.bf16.bf16.f32 " \
        "{%0,%1,%2,%3}, {%4,%5,%6,%7}, {%8,%9}, {%0,%1,%2,%3};" \
        : "+f"((d)[0]), "+f"((d)[1]), "+f"((d)[2]), "+f"((d)[3]) \
        : "r"((a)[0]), "r"((a)[1]), "r"((a)[2]), "r"((a)[3]), "r"(b0), "r"(b1))

__device__ __forceinline__ void split2(float x, float y, uint32_t& hi, uint32_t& lo) {
    __nv_bfloat162 h = __float22bfloat162_rn(make_float2(x, y));
    float rx = x - __low2float(h);
    float ry = y - __high2float(h);
    __nv_bfloat162 l = __float22bfloat162_rn(make_float2(rx, ry));
    hi = *reinterpret_cast<uint32_t*>(&h);
    lo = *reinterpret_cast<uint32_t*>(&l);
}

// ---------------- input conversion (x, qkv_w, proj_w -> split bf16) ----------
#define NX (SLEN * DIM)
#define NW1 (3 * DIM * DIM)
#define NW2 (DIM * DIM)
__global__ void convert_in(const float* __restrict__ x,
                           const float* __restrict__ w1,
                           const float* __restrict__ w2)
{
    for (size_t i = (size_t)blockIdx.x * 256 + threadIdx.x;
         i < (size_t)(NX + NW1 + NW2); i += (size_t)gridDim.x * 256) {
        float v; __nv_bfloat16 *dh, *dl; size_t j;
        if (i < NX)            { j = i;             v = x[j];  dh = g_Xh;  dl = g_Xl;  }
        else if (i < NX + NW1) { j = i - NX;        v = w1[j]; dh = g_W1h; dl = g_W1l; }
        else                   { j = i - NX - NW1;  v = w2[j]; dh = g_W2h; dl = g_W2l; }
        __nv_bfloat16 h = __float2bfloat16(v);
        dh[j] = h;
        dl[j] = __float2bfloat16(v - __bfloat162float(h));
    }
}

// ---------------- split-bf16 tensor GEMM (proven round 4) --------------------
#define TG 80
#define G_AH 0
#define G_AL (128 * TG)
#define G_BH (2 * 128 * TG)
#define G_BL (2 * 128 * TG + 64 * TG)
#define G_STG (2 * 128 * TG + 2 * 64 * TG)
#define SMEM_GEMM (2 * G_STG)

template <int MODE>
__global__ void __launch_bounds__(256) gemm_bf16(
    const __nv_bfloat16* __restrict__ Agh, const __nv_bfloat16* __restrict__ Agl,
    const __nv_bfloat16* __restrict__ Bgh, const __nv_bfloat16* __restrict__ Bgl,
    const float* __restrict__ bias, float* __restrict__ out)
{
    extern __shared__ char smem[];
    const uint32_t sb = smem_u32(smem);
    const int tid  = threadIdx.x;
    const int lane = tid & 31;
    const int warp = tid >> 5;
    const int g    = lane >> 2;
    const int tm   = lane & 3;
    const int bm   = blockIdx.y * 128;
    const int bn   = blockIdx.x * 64;
    const int qr   = warp * 16;

    auto load_tile = [&](int buf, int kt) {
        const uint32_t st = sb + buf * G_STG;
        const int k0 = kt * 32;
#pragma unroll
        for (int rep = 0; rep < 6; rep++) {
            int c = tid + rep * 256;
            if (c < 512) {
                int row = c >> 2, off = c & 3;
                CP_ASYNC16(st + G_AH + row * TG + off * 16,
                           Agh + (size_t)(bm + row) * DIM + k0 + off * 8);
            } else if (c < 1024) {
                int cc = c - 512, row = cc >> 2, off = cc & 3;
                CP_ASYNC16(st + G_AL + row * TG + off * 16,
                           Agl + (size_t)(bm + row) * DIM + k0 + off * 8);
            } else if (c < 1280) {
                int cc = c - 1024, row = cc >> 2, off = cc & 3;
                CP_ASYNC16(st + G_BH + row * TG + off * 16,
                           Bgh + (size_t)(bn + row) * DIM + k0 + off * 8);
            } else {
                int cc = c - 1280, row = cc >> 2, off = cc & 3;
                CP_ASYNC16(st + G_BL + row * TG + off * 16,
                           Bgl + (size_t)(bn + row) * DIM + k0 + off * 8);
            }
        }
    };

    const uint32_t arow = (uint32_t)((lane & 15) * TG + (lane >> 4) * 16) + qr * TG;
    const uint32_t brow = (uint32_t)((lane & 7) * TG + (((lane & 15) >> 3) << 4));

    float sc[8][4];
#pragma unroll
    for (int nb = 0; nb < 8; nb++)
#pragma unroll
        for (int j = 0; j < 4; j++) sc[nb][j] = 0.0f;

    load_tile(0, 0);
    CP_COMMIT();

    for (int kt = 0; kt < 24; kt++) {
        if (kt < 23) { load_tile((kt + 1) & 1, kt + 1); CP_COMMIT(); CP_WAIT1(); }
        else         { CP_WAIT0(); }
        __syncthreads();

        const uint32_t st = sb + (kt & 1) * G_STG;
#pragma unroll
        for (int ks = 0; ks < 2; ks++) {
            uint32_t ah[4], al[4];
            LDSM_X4(ah[0], ah[1], ah[2], ah[3], st + G_AH + arow + ks * 32);
            LDSM_X4(al[0], al[1], al[2], al[3], st + G_AL + arow + ks * 32);
#pragma unroll
            for (int nb = 0; nb < 8; nb++) {
                uint32_t bh0, bh1, bl0, bl1;
                LDSM_X2(bh0, bh1, st + G_BH + brow + nb * (8 * TG) + ks * 32);
                LDSM_X2(bl0, bl1, st + G_BL + brow + nb * (8 * TG) + ks * 32);
                MMA16816(sc[nb], ah, bh0, bh1);
                MMA16816(sc[nb], ah, bl0, bl1);
                MMA16816(sc[nb], al, bh0, bh1);
            }
        }
        __syncthreads();
    }

    const int r0 = bm + qr + g, r1 = r0 + 8;
    if (MODE == 1) {
#pragma unroll
        for (int nb = 0; nb < 8; nb++) {
            const int jj = bn + nb * 8 + tm * 2;
            const float b0 = bias[jj], b1 = bias[jj + 1];
            *(float2*)&out[(size_t)r0 * DIM + jj] = make_float2(sc[nb][0] + b0, sc[nb][1] + b1);
            *(float2*)&out[(size_t)r1 * DIM + jj] = make_float2(sc[nb][2] + b0, sc[nb][3] + b1);
        }
    } else {
        const int which = bn / DIM;
        const int head  = (bn % DIM) >> 6;
#pragma unroll
        for (int nb = 0; nb < 8; nb++) {
            const int jj  = bn + nb * 8 + tm * 2;
            const int col = nb * 8 + tm * 2;
            const float b0 = bias[jj], b1 = bias[jj + 1];
            float v00 = sc[nb][0] + b0, v01 = sc[nb][1] + b1;
            float v10 = sc[nb][2] + b0, v11 = sc[nb][3] + b1;
            if (which == 0) {
                uint32_t h, l;
                split2(v00 * 0.125f, v01 * 0.125f, h, l);
                *(uint32_t*)&g_Qh[((size_t)head * SLEN + r0) * HD + col] = h;
                *(uint32_t*)&g_Ql[((size_t)head * SLEN + r0) * HD + col] = l;
                split2(v10 * 0.125f, v11 * 0.125f, h, l);
                *(uint32_t*)&g_Qh[((size_t)head * SLEN + r1) * HD + col] = h;
                *(uint32_t*)&g_Ql[((size_t)head * SLEN + r1) * HD + col] = l;
            } else if (which == 1) {
                uint32_t h, l;
                split2(v00, v01, h, l);
                *(uint32_t*)&g_Kh[((size_t)head * SLEN + r0) * HD + col] = h;
                *(uint32_t*)&g_Kl[((size_t)head * SLEN + r0) * HD + col] = l;
                split2(v10, v11, h, l);
                *(uint32_t*)&g_Kh[((size_t)head * SLEN + r1) * HD + col] = h;
                *(uint32_t*)&g_Kl[((size_t)head * SLEN + r1) * HD + col] = l;
            } else {
                float vv[4] = {v00, v01, v10, v11};
                int rr[4] = {r0, r0, r1, r1};
                int cc[4] = {col, col + 1, col, col + 1};
#pragma unroll
                for (int e = 0; e < 4; e++) {
                    __nv_bfloat16 h = __float2bfloat16(vv[e]);
                    size_t ti = ((size_t)head * HD + cc[e]) * SLEN + rr[e];
                    g_Vth[ti] = h;
                    g_Vtl[ti] = __float2bfloat16(vv[e] - __bfloat162float(h));
                }
            }
        }
    }
}

// ---------------- rel-pos bias (merged h/w; Q from split) --------------------
#define REL_SM_FLOATS (64 * 68 + 127 * 65)
__global__ void rel_kernel(const float* __restrict__ rph,
                           const float* __restrict__ rpw)
{
    extern __shared__ float sm[];
    float* Qs = sm;
    float* R  = sm + 64 * 68;
    const int qh = blockIdx.x, head = blockIdx.y;
    const int isW = blockIdx.z;
    const float* relpos = isW ? rpw : rph;
    const int tid = threadIdx.x;
    const int tx = tid & 15, ty = tid >> 4;

    const __nv_bfloat16* Qhg = &g_Qh[((size_t)head * SLEN + qh * GRD) * HD];
    const __nv_bfloat16* Qlg = &g_Ql[((size_t)head * SLEN + qh * GRD) * HD];
    for (int t = tid; t < 4096; t += 256) {
        int c = t & 63, qw = t >> 6;
        Qs[c * 68 + qw] = 8.0f * (__bfloat162float(Qhg[(size_t)qw * HD + c]) +
                                  __bfloat162float(Qlg[(size_t)qw * HD + c]));
    }

    if (!isW) {
        for (int t = tid; t < 4096; t += 256) {
            int c = t & 63, kh = t >> 6;
            R[c * 68 + kh] = relpos[(qh - kh + 63) * 64 + c];
        }
        __syncthreads();
        float acc[4][4] = {};
#pragma unroll 4
        for (int c = 0; c < 64; c++) {
            float4 a = *(const float4*)&Qs[c * 68 + (ty << 2)];
            float4 b = *(const float4*)&R[c * 68 + (tx << 2)];
            float av[4] = {a.x, a.y, a.z, a.w};
            float bv[4] = {b.x, b.y, b.z, b.w};
#pragma unroll
            for (int i = 0; i < 4; i++)
#pragma unroll
                for (int j = 0; j < 4; j++) acc[i][j] += av[i] * bv[j];
        }
#pragma unroll
        for (int i = 0; i < 4; i++)
#pragma unroll
            for (int j = 0; j < 4; j++) {
                int qw = (ty << 2) + i, kh = (tx << 2) + j;
                g_relh[((size_t)head * SLEN + qh * 64 + qw) * 64 + kh] = acc[i][j];
            }
    } else {
        for (int t = tid; t < 127 * 64; t += 256) {
            int c = t & 63, rr = t >> 6;
            R[rr * 65 + c] = relpos[rr * 64 + c];
        }
        __syncthreads();
        float acc[4][4] = {};
        const int qwb = ty << 2, kwb = tx << 2;
        for (int c = 0; c < 64; c++) {
            float4 a = *(const float4*)&Qs[c * 68 + qwb];
            float av[4] = {a.x, a.y, a.z, a.w};
#pragma unroll
            for (int i = 0; i < 4; i++)
#pragma unroll
                for (int j = 0; j < 4; j++)
                    acc[i][j] += av[i] * R[(qwb + i - kwb - j + 63) * 65 + c];
        }
#pragma unroll
        for (int i = 0; i < 4; i++)
#pragma unroll
            for (int j = 0; j < 4; j++) {
                int qw = qwb + i, kw = kwb + j;
                g_relw[((size_t)head * SLEN + qh * 64 + qw) * 64 + kw] = acc[i][j];
            }
    }
}

// ---------------- mma.sync flash attention (key-tile 32, 3 CTAs/SM) ----------
// 128 threads = 4 warps; q-tile 64; key-tile 32 (half a key-grid row).
// smem 72704 B/CTA -> 3 CTAs/SM = 12 warps/SM for latency hiding.
#define KROW 144
#define VROW 80
#define KST(b)  ((b) * 9216)                  // KH(4608) + KL(4608)
#define VST(b)  (18432 + (b) * 10240)         // VH(5120) + VL(5120)
#define RH_OFF  38912
#define RW_OFF  (RH_OFF + 64 * 66 * 4)
#define SMEM_ATTN (RW_OFF + 64 * 66 * 4)      // 72704

__global__ void __launch_bounds__(128, 3) attn_mma_kernel()
{
    extern __shared__ char smem[];
    const uint32_t sb = smem_u32(smem);
    const int tid  = threadIdx.x;
    const int lane = tid & 31;
    const int warp = tid >> 5;
    const int g    = lane >> 2;
    const int tm   = lane & 3;
    const int head = blockIdx.y;
    const int q0   = blockIdx.x * 64;
    const int qr   = warp * 16;

    float* rhS = (float*)(smem + RH_OFF);
    float* rwS = (float*)(smem + RW_OFF);

    // rel tables (pre-scaled by log2(e): softmax runs base-2)
    for (int t = tid; t < 4096; t += 128) {
        int row = t >> 6, k = t & 63;
        rhS[row * 66 + k] = LOG2E * g_relh[((size_t)head * SLEN + q0 + row) * 64 + k];
        rwS[row * 66 + k] = LOG2E * g_relw[((size_t)head * SLEN + q0 + row) * 64 + k];
    }

    uint32_t qhf[4][4], qlf[4][4];
    {
        const uint32_t* q0h = (const uint32_t*)(g_Qh + ((size_t)head * SLEN + q0 + qr + g) * HD);
        const uint32_t* q1h = (const uint32_t*)(g_Qh + ((size_t)head * SLEN + q0 + qr + g + 8) * HD);
        const uint32_t* q0l = (const uint32_t*)(g_Ql + ((size_t)head * SLEN + q0 + qr + g) * HD);
        const uint32_t* q1l = (const uint32_t*)(g_Ql + ((size_t)head * SLEN + q0 + qr + g + 8) * HD);
#pragma unroll
        for (int ks = 0; ks < 4; ks++) {
            qhf[ks][0] = q0h[ks * 8 + tm];     qhf[ks][1] = q1h[ks * 8 + tm];
            qhf[ks][2] = q0h[ks * 8 + tm + 4]; qhf[ks][3] = q1h[ks * 8 + tm + 4];
            qlf[ks][0] = q0l[ks * 8 + tm];     qlf[ks][1] = q1l[ks * 8 + tm];
            qlf[ks][2] = q0l[ks * 8 + tm + 4]; qlf[ks][3] = q1l[ks * 8 + tm + 4];
        }
    }

    const uint32_t kb4 = (uint32_t)((lane & 7) * KROW + ((lane >> 3) & 1) * 16 +
                                    ((lane >> 4) & 1) * (8 * KROW));
    const uint32_t vb4 = (uint32_t)((lane & 7) * VROW + ((lane >> 3) & 1) * 16 +
                                    ((lane >> 4) & 1) * (8 * VROW));

    const char* KhG = (const char*)(g_Kh + (size_t)head * SLEN * HD);
    const char* KlG = (const char*)(g_Kl + (size_t)head * SLEN * HD);
    const char* VhG = (const char*)(g_Vth + (size_t)head * HD * SLEN);
    const char* VlG = (const char*)(g_Vtl + (size_t)head * HD * SLEN);

    // K tile: 32 key-rows x 64c (128B + 16 pad). V tile: 64 c-rows x 32 keys (64B + 16 pad).
    auto load_tiles = [&](int t) {
        const uint32_t kst = sb + KST(t & 1);
        const uint32_t vst = sb + VST(t & 1);
#pragma unroll
        for (int rep = 0; rep < 4; rep++) {
            int c = tid + rep * 128;            // 0..511
            if (c < 256) {
                int row = c >> 3, off = c & 7;
                CP_ASYNC16(kst + row * KROW + off * 16,
                           KhG + (size_t)(t * 32 + row) * 128 + off * 16);
            } else {
                int cc = c - 256, row = cc >> 3, off = cc & 7;
                CP_ASYNC16(kst + 4608 + row * KROW + off * 16,
                           KlG + (size_t)(t * 32 + row) * 128 + off * 16);
            }
        }
#pragma unroll
        for (int rep = 0; rep < 4; rep++) {
            int c = tid + rep * 128;            // 0..511
            if (c < 256) {
                int row = c >> 2, off = c & 3;
                CP_ASYNC16(vst + row * VROW + off * 16,
                           VhG + (size_t)row * 8192 + (size_t)t * 64 + off * 16);
            } else {
                int cc = c - 256, row = cc >> 2, off = cc & 3;
                CP_ASYNC16(vst + 5120 + row * VROW + off * 16,
                           VlG + (size_t)row * 8192 + (size_t)t * 64 + off * 16);
            }
        }
    };

    float o[8][4];
#pragma unroll
    for (int cb = 0; cb < 8; cb++)
#pragma unroll
        for (int j = 0; j < 4; j++) o[cb][j] = 0.0f;
    float m0 = -1e30f, m1 = -1e30f, l0 = 0.0f, l1 = 0.0f;

    load_tiles(0);
    CP_COMMIT();

    for (int kt = 0; kt < 128; kt++) {
        if (kt < 127) { load_tiles(kt + 1); CP_COMMIT(); CP_WAIT1(); }
        else          { CP_WAIT0(); }
        __syncthreads();

        const uint32_t kst = sb + KST(kt & 1);
        const uint32_t kh0 = kst + kb4;
        const uint32_t kl0 = kst + 4608 + kb4;

        // ---- S = Qh Kh + Qh Kl + Ql Kh  (32 keys -> sc[4][4]) ----
        float sc[4][4];
#pragma unroll
        for (int nb = 0; nb < 4; nb++)
#pragma unroll
            for (int j = 0; j < 4; j++) sc[nb][j] = 0.0f;

#pragma unroll
        for (int ks = 0; ks < 4; ks++) {
#pragma unroll
            for (int nb2 = 0; nb2 < 2; nb2++) {
                uint32_t bh0, bh1, bh2, bh3, bl0, bl1, bl2, bl3;
                LDSM_X4(bh0, bh1, bh2, bh3, kh0 + nb2 * (16 * KROW) + ks * 32);
                LDSM_X4(bl0, bl1, bl2, bl3, kl0 + nb2 * (16 * KROW) + ks * 32);
                MMA16816(sc[2 * nb2], qhf[ks], bh0, bh1);
                MMA16816(sc[2 * nb2], qhf[ks], bl0, bl1);
                MMA16816(sc[2 * nb2], qlf[ks], bh0, bh1);
                MMA16816(sc[2 * nb2 + 1], qhf[ks], bh2, bh3);
                MMA16816(sc[2 * nb2 + 1], qhf[ks], bl2, bl3);
                MMA16816(sc[2 * nb2 + 1], qlf[ks], bh2, bh3);
            }
        }

        // ---- bias + online softmax (base-2) ----
        const int r0 = qr + g, r1 = r0 + 8;
        const int kh  = kt >> 1;                 // key-grid row
        const int kwb = (kt & 1) * 32;           // key col base within grid row
        const float rh0 = rhS[r0 * 66 + kh];
        const float rh1 = rhS[r1 * 66 + kh];
        float mt0 = -1e30f, mt1 = -1e30f;
#pragma unroll
        for (int nb = 0; nb < 4; nb++) {
            float2 w0 = *(const float2*)&rwS[r0 * 66 + kwb + nb * 8 + tm * 2];
            float2 w1 = *(const float2*)&rwS[r1 * 66 + kwb + nb * 8 + tm * 2];
            sc[nb][0] = fmaf(sc[nb][0], LOG2E, rh0 + w0.x);
            sc[nb][1] = fmaf(sc[nb][1], LOG2E, rh0 + w0.y);
            sc[nb][2] = fmaf(sc[nb][2], LOG2E, rh1 + w1.x);
            sc[nb][3] = fmaf(sc[nb][3], LOG2E, rh1 + w1.y);
            mt0 = fmaxf(mt0, fmaxf(sc[nb][0], sc[nb][1]));
            mt1 = fmaxf(mt1, fmaxf(sc[nb][2], sc[nb][3]));
        }
        mt0 = fmaxf(mt0, __shfl_xor_sync(0xffffffffu, mt0, 1));
        mt0 = fmaxf(mt0, __shfl_xor_sync(0xffffffffu, mt0, 2));
        mt1 = fmaxf(mt1, __shfl_xor_sync(0xffffffffu, mt1, 1));
        mt1 = fmaxf(mt1, __shfl_xor_sync(0xffffffffu, mt1, 2));

        const float mn0 = fmaxf(m0, mt0);
        const float mn1 = fmaxf(m1, mt1);
        const float a0 = exp2f(m0 - mn0);
        const float a1 = exp2f(m1 - mn1);
        m0 = mn0; m1 = mn1;

        float s0 = 0.0f, s1 = 0.0f;
#pragma unroll
        for (int nb = 0; nb < 4; nb++) {
            sc[nb][0] = exp2f(sc[nb][0] - mn0);
            sc[nb][1] = exp2f(sc[nb][1] - mn0);
            sc[nb][2] = exp2f(sc[nb][2] - mn1);
            sc[nb][3] = exp2f(sc[nb][3] - mn1);
            s0 += sc[nb][0] + sc[nb][1];
            s1 += sc[nb][2] + sc[nb][3];
        }
        s0 += __shfl_xor_sync(0xffffffffu, s0, 1);
        s0 += __shfl_xor_sync(0xffffffffu, s0, 2);
        s1 += __shfl_xor_sync(0xffffffffu, s1, 1);
        s1 += __shfl_xor_sync(0xffffffffu, s1, 2);
        l0 = l0 * a0 + s0;
        l1 = l1 * a1 + s1;

#pragma unroll
        for (int cb = 0; cb < 8; cb++) {
            o[cb][0] *= a0; o[cb][1] *= a0;
            o[cb][2] *= a1; o[cb][3] *= a1;
        }

        // ---- O += Ph Vh + Ph Vl + Pl Vh  (2 k16-steps) ----
        const uint32_t vst = sb + VST(kt & 1);
        const uint32_t vh0 = vst + vb4;
        const uint32_t vl0 = vst + 5120 + vb4;
#pragma unroll
        for (int kb = 0; kb < 2; kb++) {
            uint32_t ph[4], pl[4];
            split2(sc[2 * kb][0],     sc[2 * kb][1],     ph[0], pl[0]);
            split2(sc[2 * kb][2],     sc[2 * kb][3],     ph[1], pl[1]);
            split2(sc[2 * kb + 1][0], sc[2 * kb + 1][1], ph[2], pl[2]);
            split2(sc[2 * kb + 1][2], sc[2 * kb + 1][3], ph[3], pl[3]);
#pragma unroll
            for (int cb2 = 0; cb2 < 4; cb2++) {
                uint32_t bh0, bh1, bh2, bh3, bl0, bl1, bl2, bl3;
                LDSM_X4(bh0, bh1, bh2, bh3, vh0 + cb2 * (16 * VROW) + kb * 32);
                LDSM_X4(bl0, bl1, bl2, bl3, vl0 + cb2 * (16 * VROW) + kb * 32);
                MMA16816(o[2 * cb2], ph, bh0, bh1);
                MMA16816(o[2 * cb2], ph, bl0, bl1);
                MMA16816(o[2 * cb2], pl, bh0, bh1);
                MMA16816(o[2 * cb2 + 1], ph, bh2, bh3);
                MMA16816(o[2 * cb2 + 1], ph, bl2, bl3);
                MMA16816(o[2 * cb2 + 1], pl, bh2, bh3);
            }
        }
        __syncthreads();
    }

    // ---- normalize + write split-bf16 attention output ----
    const float i0 = 1.0f / l0;
    const float i1 = 1.0f / l1;
    const size_t o0 = (size_t)(q0 + qr + g) * DIM + head * HD;
    const size_t o1 = (size_t)(q0 + qr + g + 8) * DIM + head * HD;
#pragma unroll
    for (int cb = 0; cb < 8; cb++) {
        const int col = cb * 8 + tm * 2;
        uint32_t h, l;
        split2(o[cb][0] * i0, o[cb][1] * i0, h, l);
        *(uint32_t*)&g_aoh[o0 + col] = h;
        *(uint32_t*)&g_aol[o0 + col] = l;
        split2(o[cb][2] * i1, o[cb][3] * i1, h, l);
        *(uint32_t*)&g_aoh[o1 + col] = h;
        *(uint32_t*)&g_aol[o1 + col] = l;
    }
}

// ---------------- launch ------------------------------------------------------
extern "C" void kernel_launch(void* const* d_in, const int* in_sizes, int n_in,
                              void* d_out, int out_size)
{
    const float* x      = (const float*)d_in[0];
    const float* qkv_w  = (const float*)d_in[1];
    const float* qkv_b  = (const float*)d_in[2];
    const float* proj_w = (const float*)d_in[3];
    const float* proj_b = (const float*)d_in[4];
    const float* rph    = (const float*)d_in[5];
    const float* rpw    = (const float*)d_in[6];
    float* out = (float*)d_out;

    const int rel_sm = REL_SM_FLOATS * (int)sizeof(float);
    cudaFuncSetAttribute(rel_kernel, cudaFuncAttributeMaxDynamicSharedMemorySize, rel_sm);
    cudaFuncSetAttribute(attn_mma_kernel, cudaFuncAttributeMaxDynamicSharedMemorySize, SMEM_ATTN);
    cudaFuncSetAttribute(gemm_bf16<0>, cudaFuncAttributeMaxDynamicSharedMemorySize, SMEM_GEMM);
    cudaFuncSetAttribute(gemm_bf16<1>, cudaFuncAttributeMaxDynamicSharedMemorySize, SMEM_GEMM);

    __nv_bfloat16 *Xh, *Xl, *W1h, *W1l, *W2h, *W2l, *AOh, *AOl;
    cudaGetSymbolAddress((void**)&Xh,  g_Xh);
    cudaGetSymbolAddress((void**)&Xl,  g_Xl);
    cudaGetSymbolAddress((void**)&W1h, g_W1h);
    cudaGetSymbolAddress((void**)&W1l, g_W1l);
    cudaGetSymbolAddress((void**)&W2h, g_W2h);
    cudaGetSymbolAddress((void**)&W2l, g_W2l);
    cudaGetSymbolAddress((void**)&AOh, g_aoh);
    cudaGetSymbolAddress((void**)&AOl, g_aol);

    // 1) split inputs to bf16 hi/lo
    convert_in<<<2048, 256>>>(x, qkv_w, proj_w);

    // 2) qkv GEMM (tensor) -> split Q/K/V (Q pre-scaled, V transposed)
    gemm_bf16<0><<<dim3(3 * DIM / 64, SLEN / 128), 256, SMEM_GEMM>>>(
        Xh, Xl, W1h, W1l, qkv_b, nullptr);

    // 3) rel-pos bias tables (h and w fused in one launch)
    rel_kernel<<<dim3(GRD, NH, 2), 256, rel_sm>>>(rph, rpw);

    // 4) mma.sync flash attention, key-tile 32, 3 CTAs/SM
    attn_mma_kernel<<<dim3(SLEN / 64, NH), 128, SMEM_ATTN>>>();

    // 5) proj GEMM (tensor) -> out
    gemm_bf16<1><<<dim3(DIM / 64, SLEN / 128), 256, SMEM_GEMM>>>(
        AOh, AOl, W2h, W2l, proj_b, out);
}

// round 8
// speedup vs baseline: 1.2419x; 1.2052x over previous
#include <cuda_runtime.h>
#include <cuda_bf16.h>
#include <cuda_fp16.h>
#include <cstdint>

#define NH   12
#define SLEN 4096
#define HD   64
#define DIM  768
#define GRD  64
#define LOG2E 1.4426950408889634f
#define SCL2E 0.18033688011112042f   // 0.125 * log2(e)

// ---------------- scratch ----------------------------------------------------
__device__ float g_relh[NH * SLEN * GRD];
__device__ float g_relw[NH * SLEN * GRD];

// attention operands (fp16): Q split hi/lo (unscaled), K single, V^T split hi/lo
__device__ __half g_Qh[NH * SLEN * HD];
__device__ __half g_Ql[NH * SLEN * HD];
__device__ __half g_Kf[NH * SLEN * HD];
__device__ __half g_Vth[NH * HD * SLEN];   // [head][c][s]
__device__ __half g_Vtl[NH * HD * SLEN];

// GEMM operands (split bf16, proven)
__device__ __nv_bfloat16 g_Xh[SLEN * DIM];
__device__ __nv_bfloat16 g_Xl[SLEN * DIM];
__device__ __nv_bfloat16 g_W1h[3 * DIM * DIM];
__device__ __nv_bfloat16 g_W1l[3 * DIM * DIM];
__device__ __nv_bfloat16 g_W2h[DIM * DIM];
__device__ __nv_bfloat16 g_W2l[DIM * DIM];
__device__ __nv_bfloat16 g_aoh[SLEN * DIM];
__device__ __nv_bfloat16 g_aol[SLEN * DIM];

// ---------------- helpers -----------------------------------------------------
__device__ __forceinline__ uint32_t smem_u32(const void* p) {
    uint32_t a;
    asm("{ .reg .u64 t; cvta.to.shared.u64 t, %1; cvt.u32.u64 %0, t; }" : "=r"(a) : "l"(p));
    return a;
}

#define CP_ASYNC16(sm, gp) \
    asm volatile("cp.async.cg.shared.global [%0], [%1], 16;" :: "r"(sm), "l"(gp))
#define CP_COMMIT()  asm volatile("cp.async.commit_group;")
#define CP_WAIT1()   asm volatile("cp.async.wait_group 1;")
#define CP_WAIT0()   asm volatile("cp.async.wait_group 0;")

#define LDSM_X2(r0, r1, addr) \
    asm volatile("ldmatrix.sync.aligned.m8n8.x2.shared.b16 {%0,%1}, [%2];" \
                 : "=r"(r0), "=r"(r1) : "r"(addr))
#define LDSM_X4(r0, r1, r2, r3, addr) \
    asm volatile("ldmatrix.sync.aligned.m8n8.x4.shared.b16 {%0,%1,%2,%3}, [%4];" \
                 : "=r"(r0), "=r"(r1), "=r"(r2), "=r"(r3) : "r"(addr))

#define MMA16816(d, a, b0, b1) \
    asm volatile("mma.sync.aligned.m16n8k16.row.col.f32.bf16.bf16.f32 " \
        "{%0,%1,%2,%3}, {%4,%5,%6,%7}, {%8,%9}, {%0,%1,%2,%3};" \
        : "+f"((d)[0]), "+f"((d)[1]), "+f"((d)[2]), "+f"((d)[3]) \
        : "r"((a)[0]), "r"((a)[1]), "r"((a)[2]), "r"((a)[3]), "r"(b0), "r"(b1))

#define MMAH16816(d, a, b0, b1) \
    asm volatile("mma.sync.aligned.m16n8k16.row.col.f32.f16.f16.f32 " \
        "{%0,%1,%2,%3}, {%4,%5,%6,%7}, {%8,%9}, {%0,%1,%2,%3};" \
        : "+f"((d)[0]), "+f"((d)[1]), "+f"((d)[2]), "+f"((d)[3]) \
        : "r"((a)[0]), "r"((a)[1]), "r"((a)[2]), "r"((a)[3]), "r"(b0), "r"(b1))

__device__ __forceinline__ void split2(float x, float y, uint32_t& hi, uint32_t& lo) {
    __nv_bfloat162 h = __float22bfloat162_rn(make_float2(x, y));
    float rx = x - __low2float(h);
    float ry = y - __high2float(h);
    __nv_bfloat162 l = __float22bfloat162_rn(make_float2(rx, ry));
    hi = *reinterpret_cast<uint32_t*>(&h);
    lo = *reinterpret_cast<uint32_t*>(&l);
}
__device__ __forceinline__ void split2h(float x, float y, uint32_t& hi, uint32_t& lo) {
    __half2 h = __float22half2_rn(make_float2(x, y));
    float rx = x - __low2float(h);
    float ry = y - __high2float(h);
    __half2 l = __float22half2_rn(make_float2(rx, ry));
    hi = *reinterpret_cast<uint32_t*>(&h);
    lo = *reinterpret_cast<uint32_t*>(&l);
}
__device__ __forceinline__ uint32_t packh2(float x, float y) {
    __half2 h = __float22half2_rn(make_float2(x, y));
    return *reinterpret_cast<uint32_t*>(&h);
}

// ---------------- input conversion (x, qkv_w, proj_w -> split bf16) ----------
#define NX (SLEN * DIM)
#define NW1 (3 * DIM * DIM)
#define NW2 (DIM * DIM)
__global__ void convert_in(const float* __restrict__ x,
                           const float* __restrict__ w1,
                           const float* __restrict__ w2)
{
    for (size_t i = (size_t)blockIdx.x * 256 + threadIdx.x;
         i < (size_t)(NX + NW1 + NW2); i += (size_t)gridDim.x * 256) {
        float v; __nv_bfloat16 *dh, *dl; size_t j;
        if (i < NX)            { j = i;             v = x[j];  dh = g_Xh;  dl = g_Xl;  }
        else if (i < NX + NW1) { j = i - NX;        v = w1[j]; dh = g_W1h; dl = g_W1l; }
        else                   { j = i - NX - NW1;  v = w2[j]; dh = g_W2h; dl = g_W2l; }
        __nv_bfloat16 h = __float2bfloat16(v);
        dh[j] = h;
        dl[j] = __float2bfloat16(v - __bfloat162float(h));
    }
}

// ---------------- split-bf16 tensor GEMM (proven) ----------------------------
#define TG 80
#define G_AH 0
#define G_AL (128 * TG)
#define G_BH (2 * 128 * TG)
#define G_BL (2 * 128 * TG + 64 * TG)
#define G_STG (2 * 128 * TG + 2 * 64 * TG)
#define SMEM_GEMM (2 * G_STG)

template <int MODE>
__global__ void __launch_bounds__(256) gemm_bf16(
    const __nv_bfloat16* __restrict__ Agh, const __nv_bfloat16* __restrict__ Agl,
    const __nv_bfloat16* __restrict__ Bgh, const __nv_bfloat16* __restrict__ Bgl,
    const float* __restrict__ bias, float* __restrict__ out)
{
    extern __shared__ char smem[];
    const uint32_t sb = smem_u32(smem);
    const int tid  = threadIdx.x;
    const int lane = tid & 31;
    const int warp = tid >> 5;
    const int g    = lane >> 2;
    const int tm   = lane & 3;
    const int bm   = blockIdx.y * 128;
    const int bn   = blockIdx.x * 64;
    const int qr   = warp * 16;

    auto load_tile = [&](int buf, int kt) {
        const uint32_t st = sb + buf * G_STG;
        const int k0 = kt * 32;
#pragma unroll
        for (int rep = 0; rep < 6; rep++) {
            int c = tid + rep * 256;
            if (c < 512) {
                int row = c >> 2, off = c & 3;
                CP_ASYNC16(st + G_AH + row * TG + off * 16,
                           Agh + (size_t)(bm + row) * DIM + k0 + off * 8);
            } else if (c < 1024) {
                int cc = c - 512, row = cc >> 2, off = cc & 3;
                CP_ASYNC16(st + G_AL + row * TG + off * 16,
                           Agl + (size_t)(bm + row) * DIM + k0 + off * 8);
            } else if (c < 1280) {
                int cc = c - 1024, row = cc >> 2, off = cc & 3;
                CP_ASYNC16(st + G_BH + row * TG + off * 16,
                           Bgh + (size_t)(bn + row) * DIM + k0 + off * 8);
            } else {
                int cc = c - 1280, row = cc >> 2, off = cc & 3;
                CP_ASYNC16(st + G_BL + row * TG + off * 16,
                           Bgl + (size_t)(bn + row) * DIM + k0 + off * 8);
            }
        }
    };

    const uint32_t arow = (uint32_t)((lane & 15) * TG + (lane >> 4) * 16) + qr * TG;
    const uint32_t brow = (uint32_t)((lane & 7) * TG + (((lane & 15) >> 3) << 4));

    float sc[8][4];
#pragma unroll
    for (int nb = 0; nb < 8; nb++)
#pragma unroll
        for (int j = 0; j < 4; j++) sc[nb][j] = 0.0f;

    load_tile(0, 0);
    CP_COMMIT();

    for (int kt = 0; kt < 24; kt++) {
        if (kt < 23) { load_tile((kt + 1) & 1, kt + 1); CP_COMMIT(); CP_WAIT1(); }
        else         { CP_WAIT0(); }
        __syncthreads();

        const uint32_t st = sb + (kt & 1) * G_STG;
#pragma unroll
        for (int ks = 0; ks < 2; ks++) {
            uint32_t ah[4], al[4];
            LDSM_X4(ah[0], ah[1], ah[2], ah[3], st + G_AH + arow + ks * 32);
            LDSM_X4(al[0], al[1], al[2], al[3], st + G_AL + arow + ks * 32);
#pragma unroll
            for (int nb = 0; nb < 8; nb++) {
                uint32_t bh0, bh1, bl0, bl1;
                LDSM_X2(bh0, bh1, st + G_BH + brow + nb * (8 * TG) + ks * 32);
                LDSM_X2(bl0, bl1, st + G_BL + brow + nb * (8 * TG) + ks * 32);
                MMA16816(sc[nb], ah, bh0, bh1);
                MMA16816(sc[nb], ah, bl0, bl1);
                MMA16816(sc[nb], al, bh0, bh1);
            }
        }
        __syncthreads();
    }

    const int r0 = bm + qr + g, r1 = r0 + 8;
    if (MODE == 1) {
#pragma unroll
        for (int nb = 0; nb < 8; nb++) {
            const int jj = bn + nb * 8 + tm * 2;
            const float b0 = bias[jj], b1 = bias[jj + 1];
            *(float2*)&out[(size_t)r0 * DIM + jj] = make_float2(sc[nb][0] + b0, sc[nb][1] + b1);
            *(float2*)&out[(size_t)r1 * DIM + jj] = make_float2(sc[nb][2] + b0, sc[nb][3] + b1);
        }
    } else {
        const int which = bn / DIM;
        const int head  = (bn % DIM) >> 6;
#pragma unroll
        for (int nb = 0; nb < 8; nb++) {
            const int jj  = bn + nb * 8 + tm * 2;
            const int col = nb * 8 + tm * 2;
            const float b0 = bias[jj], b1 = bias[jj + 1];
            float v00 = sc[nb][0] + b0, v01 = sc[nb][1] + b1;
            float v10 = sc[nb][2] + b0, v11 = sc[nb][3] + b1;
            if (which == 0) {
                // Q unscaled, split fp16 hi/lo (scale folded into softmax)
                uint32_t h, l;
                split2h(v00, v01, h, l);
                *(uint32_t*)&g_Qh[((size_t)head * SLEN + r0) * HD + col] = h;
                *(uint32_t*)&g_Ql[((size_t)head * SLEN + r0) * HD + col] = l;
                split2h(v10, v11, h, l);
                *(uint32_t*)&g_Qh[((size_t)head * SLEN + r1) * HD + col] = h;
                *(uint32_t*)&g_Ql[((size_t)head * SLEN + r1) * HD + col] = l;
            } else if (which == 1) {
                // K single-rounded fp16
                *(uint32_t*)&g_Kf[((size_t)head * SLEN + r0) * HD + col] = packh2(v00, v01);
                *(uint32_t*)&g_Kf[((size_t)head * SLEN + r1) * HD + col] = packh2(v10, v11);
            } else {
                // V transposed, split fp16 hi/lo
                float vv[4] = {v00, v01, v10, v11};
                int rr[4] = {r0, r0, r1, r1};
                int cc[4] = {col, col + 1, col, col + 1};
#pragma unroll
                for (int e = 0; e < 4; e++) {
                    __half h = __float2half(vv[e]);
                    size_t ti = ((size_t)head * HD + cc[e]) * SLEN + rr[e];
                    g_Vth[ti] = h;
                    g_Vtl[ti] = __float2half(vv[e] - __half2float(h));
                }
            }
        }
    }
}

// ---------------- rel-pos bias (Q from fp16 split) ---------------------------
#define REL_SM_FLOATS (64 * 68 + 127 * 65)
__global__ void rel_kernel(const float* __restrict__ rph,
                           const float* __restrict__ rpw)
{
    extern __shared__ float sm[];
    float* Qs = sm;
    float* R  = sm + 64 * 68;
    const int qh = blockIdx.x, head = blockIdx.y;
    const int isW = blockIdx.z;
    const float* relpos = isW ? rpw : rph;
    const int tid = threadIdx.x;
    const int tx = tid & 15, ty = tid >> 4;

    const __half* Qhg = &g_Qh[((size_t)head * SLEN + qh * GRD) * HD];
    const __half* Qlg = &g_Ql[((size_t)head * SLEN + qh * GRD) * HD];
    for (int t = tid; t < 4096; t += 256) {
        int c = t & 63, qw = t >> 6;
        Qs[c * 68 + qw] = __half2float(Qhg[(size_t)qw * HD + c]) +
                          __half2float(Qlg[(size_t)qw * HD + c]);
    }

    if (!isW) {
        for (int t = tid; t < 4096; t += 256) {
            int c = t & 63, kh = t >> 6;
            R[c * 68 + kh] = relpos[(qh - kh + 63) * 64 + c];
        }
        __syncthreads();
        float acc[4][4] = {};
#pragma unroll 4
        for (int c = 0; c < 64; c++) {
            float4 a = *(const float4*)&Qs[c * 68 + (ty << 2)];
            float4 b = *(const float4*)&R[c * 68 + (tx << 2)];
            float av[4] = {a.x, a.y, a.z, a.w};
            float bv[4] = {b.x, b.y, b.z, b.w};
#pragma unroll
            for (int i = 0; i < 4; i++)
#pragma unroll
                for (int j = 0; j < 4; j++) acc[i][j] += av[i] * bv[j];
        }
#pragma unroll
        for (int i = 0; i < 4; i++)
#pragma unroll
            for (int j = 0; j < 4; j++) {
                int qw = (ty << 2) + i, kh = (tx << 2) + j;
                g_relh[((size_t)head * SLEN + qh * 64 + qw) * 64 + kh] = acc[i][j];
            }
    } else {
        for (int t = tid; t < 127 * 64; t += 256) {
            int c = t & 63, rr = t >> 6;
            R[rr * 65 + c] = relpos[rr * 64 + c];
        }
        __syncthreads();
        float acc[4][4] = {};
        const int qwb = ty << 2, kwb = tx << 2;
        for (int c = 0; c < 64; c++) {
            float4 a = *(const float4*)&Qs[c * 68 + qwb];
            float av[4] = {a.x, a.y, a.z, a.w};
#pragma unroll
            for (int i = 0; i < 4; i++)
#pragma unroll
                for (int j = 0; j < 4; j++)
                    acc[i][j] += av[i] * R[(qwb + i - kwb - j + 63) * 65 + c];
        }
#pragma unroll
        for (int i = 0; i < 4; i++)
#pragma unroll
            for (int j = 0; j < 4; j++) {
                int qw = qwb + i, kw = kwb + j;
                g_relw[((size_t)head * SLEN + qh * 64 + qw) * 64 + kw] = acc[i][j];
            }
    }
}

// ---------------- fp16 2-pass flash attention --------------------------------
// 128 threads = 4 warps; q-tile 64; key-tile 64. S = (Qh+Ql)·K1p ;
// O += P1p·(Vh+Vl). 2 MMA passes per GEMM instead of 3.
#define TROW     144
#define KST(b)   ((b) * 9216)                 // K single tile per stage
#define VST(b)   (18432 + (b) * 18432)        // Vh(9216) + Vl(9216) per stage
#define RH_OFF   55296
#define RW_OFF   (RH_OFF + 64 * 66 * 4)
#define SMEM_ATTN (RW_OFF + 64 * 66 * 4)      // 89088

__global__ void __launch_bounds__(128, 2) attn_mma_kernel()
{
    extern __shared__ char smem[];
    const uint32_t sb = smem_u32(smem);
    const int tid  = threadIdx.x;
    const int lane = tid & 31;
    const int warp = tid >> 5;
    const int g    = lane >> 2;
    const int tm   = lane & 3;
    const int head = blockIdx.y;
    const int q0   = blockIdx.x * 64;
    const int qr   = warp * 16;

    float* rhS = (float*)(smem + RH_OFF);
    float* rwS = (float*)(smem + RW_OFF);

    // rel tables pre-scaled by log2(e)
    for (int t = tid; t < 4096; t += 128) {
        int row = t >> 6, k = t & 63;
        rhS[row * 66 + k] = LOG2E * g_relh[((size_t)head * SLEN + q0 + row) * 64 + k];
        rwS[row * 66 + k] = LOG2E * g_relw[((size_t)head * SLEN + q0 + row) * 64 + k];
    }

    uint32_t qhf[4][4], qlf[4][4];
    {
        const uint32_t* q0h = (const uint32_t*)(g_Qh + ((size_t)head * SLEN + q0 + qr + g) * HD);
        const uint32_t* q1h = (const uint32_t*)(g_Qh + ((size_t)head * SLEN + q0 + qr + g + 8) * HD);
        const uint32_t* q0l = (const uint32_t*)(g_Ql + ((size_t)head * SLEN + q0 + qr + g) * HD);
        const uint32_t* q1l = (const uint32_t*)(g_Ql + ((size_t)head * SLEN + q0 + qr + g + 8) * HD);
#pragma unroll
        for (int ks = 0; ks < 4; ks++) {
            qhf[ks][0] = q0h[ks * 8 + tm];     qhf[ks][1] = q1h[ks * 8 + tm];
            qhf[ks][2] = q0h[ks * 8 + tm + 4]; qhf[ks][3] = q1h[ks * 8 + tm + 4];
            qlf[ks][0] = q0l[ks * 8 + tm];     qlf[ks][1] = q1l[ks * 8 + tm];
            qlf[ks][2] = q0l[ks * 8 + tm + 4]; qlf[ks][3] = q1l[ks * 8 + tm + 4];
        }
    }

    const uint32_t b4off = (uint32_t)((lane & 7) * TROW + ((lane >> 3) & 1) * 16 +
                                      ((lane >> 4) & 1) * (8 * TROW));

    const char* KG  = (const char*)(g_Kf + (size_t)head * SLEN * HD);
    const char* VhG = (const char*)(g_Vth + (size_t)head * HD * SLEN);
    const char* VlG = (const char*)(g_Vtl + (size_t)head * HD * SLEN);

    auto load_tiles = [&](int buf, int kt) {
        const uint32_t kst = sb + KST(buf);
        const uint32_t vst = sb + VST(buf);
#pragma unroll
        for (int rep = 0; rep < 4; rep++) {
            int c = tid + rep * 128;
            int row = c >> 3, off = c & 7;
            CP_ASYNC16(kst + row * TROW + off * 16,
                       KG + (size_t)(kt * 64 + row) * 128 + off * 16);
            CP_ASYNC16(vst + row * TROW + off * 16,
                       VhG + (size_t)row * 8192 + (size_t)kt * 128 + off * 16);
            CP_ASYNC16(vst + 9216 + row * TROW + off * 16,
                       VlG + (size_t)row * 8192 + (size_t)kt * 128 + off * 16);
        }
    };

    float o[8][4];
#pragma unroll
    for (int cb = 0; cb < 8; cb++)
#pragma unroll
        for (int j = 0; j < 4; j++) o[cb][j] = 0.0f;
    float m0 = -1e30f, m1 = -1e30f, l0 = 0.0f, l1 = 0.0f;

    load_tiles(0, 0);
    CP_COMMIT();

    for (int kt = 0; kt < 64; kt++) {
        if (kt < 63) { load_tiles((kt + 1) & 1, kt + 1); CP_COMMIT(); CP_WAIT1(); }
        else         { CP_WAIT0(); }
        __syncthreads();

        const uint32_t kh0 = sb + KST(kt & 1) + b4off;

        // ---- S = (Qh + Ql) · K   (2 passes) ----
        float sc[8][4];
#pragma unroll
        for (int nb = 0; nb < 8; nb++)
#pragma unroll
            for (int j = 0; j < 4; j++) sc[nb][j] = 0.0f;

#pragma unroll
        for (int ks = 0; ks < 4; ks++) {
#pragma unroll
            for (int nb2 = 0; nb2 < 4; nb2++) {
                uint32_t b0, b1, b2, b3;
                LDSM_X4(b0, b1, b2, b3, kh0 + nb2 * (16 * TROW) + ks * 32);
                MMAH16816(sc[2 * nb2], qhf[ks], b0, b1);
                MMAH16816(sc[2 * nb2], qlf[ks], b0, b1);
                MMAH16816(sc[2 * nb2 + 1], qhf[ks], b2, b3);
                MMAH16816(sc[2 * nb2 + 1], qlf[ks], b2, b3);
            }
        }

        // ---- bias + online softmax (base-2; 0.125 scale folded in) ----
        const int r0 = qr + g, r1 = r0 + 8;
        const float rh0 = rhS[r0 * 66 + kt];
        const float rh1 = rhS[r1 * 66 + kt];
        float mt0 = -1e30f, mt1 = -1e30f;
#pragma unroll
        for (int nb = 0; nb < 8; nb++) {
            float2 w0 = *(const float2*)&rwS[r0 * 66 + nb * 8 + tm * 2];
            float2 w1 = *(const float2*)&rwS[r1 * 66 + nb * 8 + tm * 2];
            sc[nb][0] = fmaf(sc[nb][0], SCL2E, rh0 + w0.x);
            sc[nb][1] = fmaf(sc[nb][1], SCL2E, rh0 + w0.y);
            sc[nb][2] = fmaf(sc[nb][2], SCL2E, rh1 + w1.x);
            sc[nb][3] = fmaf(sc[nb][3], SCL2E, rh1 + w1.y);
            mt0 = fmaxf(mt0, fmaxf(sc[nb][0], sc[nb][1]));
            mt1 = fmaxf(mt1, fmaxf(sc[nb][2], sc[nb][3]));
        }
        mt0 = fmaxf(mt0, __shfl_xor_sync(0xffffffffu, mt0, 1));
        mt0 = fmaxf(mt0, __shfl_xor_sync(0xffffffffu, mt0, 2));
        mt1 = fmaxf(mt1, __shfl_xor_sync(0xffffffffu, mt1, 1));
        mt1 = fmaxf(mt1, __shfl_xor_sync(0xffffffffu, mt1, 2));

        const float mn0 = fmaxf(m0, mt0);
        const float mn1 = fmaxf(m1, mt1);
        const float a0 = exp2f(m0 - mn0);
        const float a1 = exp2f(m1 - mn1);
        m0 = mn0; m1 = mn1;

        float s0 = 0.0f, s1 = 0.0f;
#pragma unroll
        for (int nb = 0; nb < 8; nb++) {
            sc[nb][0] = exp2f(sc[nb][0] - mn0);
            sc[nb][1] = exp2f(sc[nb][1] - mn0);
            sc[nb][2] = exp2f(sc[nb][2] - mn1);
            sc[nb][3] = exp2f(sc[nb][3] - mn1);
            s0 += sc[nb][0] + sc[nb][1];
            s1 += sc[nb][2] + sc[nb][3];
        }
        s0 += __shfl_xor_sync(0xffffffffu, s0, 1);
        s0 += __shfl_xor_sync(0xffffffffu, s0, 2);
        s1 += __shfl_xor_sync(0xffffffffu, s1, 1);
        s1 += __shfl_xor_sync(0xffffffffu, s1, 2);
        l0 = l0 * a0 + s0;
        l1 = l1 * a1 + s1;

#pragma unroll
        for (int cb = 0; cb < 8; cb++) {
            o[cb][0] *= a0; o[cb][1] *= a0;
            o[cb][2] *= a1; o[cb][3] *= a1;
        }

        // ---- O += P · (Vh + Vl)   (2 passes; P single fp16) ----
        const uint32_t vst = sb + VST(kt & 1);
        const uint32_t vh0 = vst + b4off;
        const uint32_t vl0 = vst + 9216 + b4off;
#pragma unroll
        for (int kb = 0; kb < 4; kb++) {
            uint32_t ph[4];
            ph[0] = packh2(sc[2 * kb][0],     sc[2 * kb][1]);
            ph[1] = packh2(sc[2 * kb][2],     sc[2 * kb][3]);
            ph[2] = packh2(sc[2 * kb + 1][0], sc[2 * kb + 1][1]);
            ph[3] = packh2(sc[2 * kb + 1][2], sc[2 * kb + 1][3]);
#pragma unroll
            for (int cb2 = 0; cb2 < 4; cb2++) {
                uint32_t h0, h1, h2, h3, e0, e1, e2, e3;
                LDSM_X4(h0, h1, h2, h3, vh0 + cb2 * (16 * TROW) + kb * 32);
                LDSM_X4(e0, e1, e2, e3, vl0 + cb2 * (16 * TROW) + kb * 32);
                MMAH16816(o[2 * cb2], ph, h0, h1);
                MMAH16816(o[2 * cb2], ph, e0, e1);
                MMAH16816(o[2 * cb2 + 1], ph, h2, h3);
                MMAH16816(o[2 * cb2 + 1], ph, e2, e3);
            }
        }
        __syncthreads();
    }

    // ---- normalize + write split-bf16 attention output ----
    const float i0 = 1.0f / l0;
    const float i1 = 1.0f / l1;
    const size_t o0 = (size_t)(q0 + qr + g) * DIM + head * HD;
    const size_t o1 = (size_t)(q0 + qr + g + 8) * DIM + head * HD;
#pragma unroll
    for (int cb = 0; cb < 8; cb++) {
        const int col = cb * 8 + tm * 2;
        uint32_t h, l;
        split2(o[cb][0] * i0, o[cb][1] * i0, h, l);
        *(uint32_t*)&g_aoh[o0 + col] = h;
        *(uint32_t*)&g_aol[o0 + col] = l;
        split2(o[cb][2] * i1, o[cb][3] * i1, h, l);
        *(uint32_t*)&g_aoh[o1 + col] = h;
        *(uint32_t*)&g_aol[o1 + col] = l;
    }
}

// ---------------- launch ------------------------------------------------------
extern "C" void kernel_launch(void* const* d_in, const int* in_sizes, int n_in,
                              void* d_out, int out_size)
{
    const float* x      = (const float*)d_in[0];
    const float* qkv_w  = (const float*)d_in[1];
    const float* qkv_b  = (const float*)d_in[2];
    const float* proj_w = (const float*)d_in[3];
    const float* proj_b = (const float*)d_in[4];
    const float* rph    = (const float*)d_in[5];
    const float* rpw    = (const float*)d_in[6];
    float* out = (float*)d_out;

    const int rel_sm = REL_SM_FLOATS * (int)sizeof(float);
    cudaFuncSetAttribute(rel_kernel, cudaFuncAttributeMaxDynamicSharedMemorySize, rel_sm);
    cudaFuncSetAttribute(attn_mma_kernel, cudaFuncAttributeMaxDynamicSharedMemorySize, SMEM_ATTN);
    cudaFuncSetAttribute(gemm_bf16<0>, cudaFuncAttributeMaxDynamicSharedMemorySize, SMEM_GEMM);
    cudaFuncSetAttribute(gemm_bf16<1>, cudaFuncAttributeMaxDynamicSharedMemorySize, SMEM_GEMM);

    __nv_bfloat16 *Xh, *Xl, *W1h, *W1l, *W2h, *W2l, *AOh, *AOl;
    cudaGetSymbolAddress((void**)&Xh,  g_Xh);
    cudaGetSymbolAddress((void**)&Xl,  g_Xl);
    cudaGetSymbolAddress((void**)&W1h, g_W1h);
    cudaGetSymbolAddress((void**)&W1l, g_W1l);
    cudaGetSymbolAddress((void**)&W2h, g_W2h);
    cudaGetSymbolAddress((void**)&W2l, g_W2l);
    cudaGetSymbolAddress((void**)&AOh, g_aoh);
    cudaGetSymbolAddress((void**)&AOl, g_aol);

    // 1) split inputs to bf16 hi/lo
    convert_in<<<2048, 256>>>(x, qkv_w, proj_w);

    // 2) qkv GEMM (tensor) -> fp16 Q split / K single / V^T split
    gemm_bf16<0><<<dim3(3 * DIM / 64, SLEN / 128), 256, SMEM_GEMM>>>(
        Xh, Xl, W1h, W1l, qkv_b, nullptr);

    // 3) rel-pos bias tables
    rel_kernel<<<dim3(GRD, NH, 2), 256, rel_sm>>>(rph, rpw);

    // 4) fp16 2-pass flash attention
    attn_mma_kernel<<<dim3(SLEN / 64, NH), 128, SMEM_ATTN>>>();

    // 5) proj GEMM (tensor) -> out
    gemm_bf16<1><<<dim3(DIM / 64, SLEN / 128), 256, SMEM_GEMM>>>(
        AOh, AOl, W2h, W2l, proj_b, out);
}

// round 9
// speedup vs baseline: 1.4839x; 1.1948x over previous
#include <cuda_runtime.h>
#include <cuda_bf16.h>
#include <cuda_fp16.h>
#include <cstdint>

#define NH   12
#define SLEN 4096
#define HD   64
#define DIM  768
#define GRD  64
#define LOG2E 1.4426950408889634f
#define SCL2E 0.18033688011112042f   // 0.125 * log2(e)

// ---------------- scratch ----------------------------------------------------
__device__ float g_relh[NH * SLEN * GRD];
__device__ float g_relw[NH * SLEN * GRD];

// attention operands (fp16 single-rounded; fp32-grade values from split GEMM)
__device__ __half g_Qf[NH * SLEN * HD];    // unscaled
__device__ __half g_Kf[NH * SLEN * HD];
__device__ __half g_Vt[NH * HD * SLEN];    // [head][c][s]

// GEMM operands (split bf16, proven)
__device__ __nv_bfloat16 g_Xh[SLEN * DIM];
__device__ __nv_bfloat16 g_Xl[SLEN * DIM];
__device__ __nv_bfloat16 g_W1h[3 * DIM * DIM];
__device__ __nv_bfloat16 g_W1l[3 * DIM * DIM];
__device__ __nv_bfloat16 g_W2h[DIM * DIM];
__device__ __nv_bfloat16 g_W2l[DIM * DIM];
__device__ __nv_bfloat16 g_aoh[SLEN * DIM];
__device__ __nv_bfloat16 g_aol[SLEN * DIM];

// ---------------- helpers -----------------------------------------------------
__device__ __forceinline__ uint32_t smem_u32(const void* p) {
    uint32_t a;
    asm("{ .reg .u64 t; cvta.to.shared.u64 t, %1; cvt.u32.u64 %0, t; }" : "=r"(a) : "l"(p));
    return a;
}

#define CP_ASYNC16(sm, gp) \
    asm volatile("cp.async.cg.shared.global [%0], [%1], 16;" :: "r"(sm), "l"(gp))
#define CP_COMMIT()  asm volatile("cp.async.commit_group;")
#define CP_WAIT1()   asm volatile("cp.async.wait_group 1;")
#define CP_WAIT0()   asm volatile("cp.async.wait_group 0;")

#define LDSM_X2(r0, r1, addr) \
    asm volatile("ldmatrix.sync.aligned.m8n8.x2.shared.b16 {%0,%1}, [%2];" \
                 : "=r"(r0), "=r"(r1) : "r"(addr))
#define LDSM_X4(r0, r1, r2, r3, addr) \
    asm volatile("ldmatrix.sync.aligned.m8n8.x4.shared.b16 {%0,%1,%2,%3}, [%4];" \
                 : "=r"(r0), "=r"(r1), "=r"(r2), "=r"(r3) : "r"(addr))

#define MMA16816(d, a, b0, b1) \
    asm volatile("mma.sync.aligned.m16n8k16.row.col.f32.bf16.bf16.f32 " \
        "{%0,%1,%2,%3}, {%4,%5,%6,%7}, {%8,%9}, {%0,%1,%2,%3};" \
        : "+f"((d)[0]), "+f"((d)[1]), "+f"((d)[2]), "+f"((d)[3]) \
        : "r"((a)[0]), "r"((a)[1]), "r"((a)[2]), "r"((a)[3]), "r"(b0), "r"(b1))

#define MMAH16816(d, a, b0, b1) \
    asm volatile("mma.sync.aligned.m16n8k16.row.col.f32.f16.f16.f32 " \
        "{%0,%1,%2,%3}, {%4,%5,%6,%7}, {%8,%9}, {%0,%1,%2,%3};" \
        : "+f"((d)[0]), "+f"((d)[1]), "+f"((d)[2]), "+f"((d)[3]) \
        : "r"((a)[0]), "r"((a)[1]), "r"((a)[2]), "r"((a)[3]), "r"(b0), "r"(b1))

__device__ __forceinline__ void split2(float x, float y, uint32_t& hi, uint32_t& lo) {
    __nv_bfloat162 h = __float22bfloat162_rn(make_float2(x, y));
    float rx = x - __low2float(h);
    float ry = y - __high2float(h);
    __nv_bfloat162 l = __float22bfloat162_rn(make_float2(rx, ry));
    hi = *reinterpret_cast<uint32_t*>(&h);
    lo = *reinterpret_cast<uint32_t*>(&l);
}
__device__ __forceinline__ uint32_t packh2(float x, float y) {
    __half2 h = __float22half2_rn(make_float2(x, y));
    return *reinterpret_cast<uint32_t*>(&h);
}

// ---------------- input conversion (x, qkv_w, proj_w -> split bf16) ----------
#define NX (SLEN * DIM)
#define NW1 (3 * DIM * DIM)
#define NW2 (DIM * DIM)
__global__ void convert_in(const float* __restrict__ x,
                           const float* __restrict__ w1,
                           const float* __restrict__ w2)
{
    for (size_t i = (size_t)blockIdx.x * 256 + threadIdx.x;
         i < (size_t)(NX + NW1 + NW2); i += (size_t)gridDim.x * 256) {
        float v; __nv_bfloat16 *dh, *dl; size_t j;
        if (i < NX)            { j = i;             v = x[j];  dh = g_Xh;  dl = g_Xl;  }
        else if (i < NX + NW1) { j = i - NX;        v = w1[j]; dh = g_W1h; dl = g_W1l; }
        else                   { j = i - NX - NW1;  v = w2[j]; dh = g_W2h; dl = g_W2l; }
        __nv_bfloat16 h = __float2bfloat16(v);
        dh[j] = h;
        dl[j] = __float2bfloat16(v - __bfloat162float(h));
    }
}

// ---------------- split-bf16 tensor GEMM (proven) ----------------------------
#define TG 80
#define G_AH 0
#define G_AL (128 * TG)
#define G_BH (2 * 128 * TG)
#define G_BL (2 * 128 * TG + 64 * TG)
#define G_STG (2 * 128 * TG + 2 * 64 * TG)
#define SMEM_GEMM (2 * G_STG)

template <int MODE>
__global__ void __launch_bounds__(256) gemm_bf16(
    const __nv_bfloat16* __restrict__ Agh, const __nv_bfloat16* __restrict__ Agl,
    const __nv_bfloat16* __restrict__ Bgh, const __nv_bfloat16* __restrict__ Bgl,
    const float* __restrict__ bias, float* __restrict__ out)
{
    extern __shared__ char smem[];
    const uint32_t sb = smem_u32(smem);
    const int tid  = threadIdx.x;
    const int lane = tid & 31;
    const int warp = tid >> 5;
    const int g    = lane >> 2;
    const int tm   = lane & 3;
    const int bm   = blockIdx.y * 128;
    const int bn   = blockIdx.x * 64;
    const int qr   = warp * 16;

    auto load_tile = [&](int buf, int kt) {
        const uint32_t st = sb + buf * G_STG;
        const int k0 = kt * 32;
#pragma unroll
        for (int rep = 0; rep < 6; rep++) {
            int c = tid + rep * 256;
            if (c < 512) {
                int row = c >> 2, off = c & 3;
                CP_ASYNC16(st + G_AH + row * TG + off * 16,
                           Agh + (size_t)(bm + row) * DIM + k0 + off * 8);
            } else if (c < 1024) {
                int cc = c - 512, row = cc >> 2, off = cc & 3;
                CP_ASYNC16(st + G_AL + row * TG + off * 16,
                           Agl + (size_t)(bm + row) * DIM + k0 + off * 8);
            } else if (c < 1280) {
                int cc = c - 1024, row = cc >> 2, off = cc & 3;
                CP_ASYNC16(st + G_BH + row * TG + off * 16,
                           Bgh + (size_t)(bn + row) * DIM + k0 + off * 8);
            } else {
                int cc = c - 1280, row = cc >> 2, off = cc & 3;
                CP_ASYNC16(st + G_BL + row * TG + off * 16,
                           Bgl + (size_t)(bn + row) * DIM + k0 + off * 8);
            }
        }
    };

    const uint32_t arow = (uint32_t)((lane & 15) * TG + (lane >> 4) * 16) + qr * TG;
    const uint32_t brow = (uint32_t)((lane & 7) * TG + (((lane & 15) >> 3) << 4));

    float sc[8][4];
#pragma unroll
    for (int nb = 0; nb < 8; nb++)
#pragma unroll
        for (int j = 0; j < 4; j++) sc[nb][j] = 0.0f;

    load_tile(0, 0);
    CP_COMMIT();

    for (int kt = 0; kt < 24; kt++) {
        if (kt < 23) { load_tile((kt + 1) & 1, kt + 1); CP_COMMIT(); CP_WAIT1(); }
        else         { CP_WAIT0(); }
        __syncthreads();

        const uint32_t st = sb + (kt & 1) * G_STG;
#pragma unroll
        for (int ks = 0; ks < 2; ks++) {
            uint32_t ah[4], al[4];
            LDSM_X4(ah[0], ah[1], ah[2], ah[3], st + G_AH + arow + ks * 32);
            LDSM_X4(al[0], al[1], al[2], al[3], st + G_AL + arow + ks * 32);
#pragma unroll
            for (int nb = 0; nb < 8; nb++) {
                uint32_t bh0, bh1, bl0, bl1;
                LDSM_X2(bh0, bh1, st + G_BH + brow + nb * (8 * TG) + ks * 32);
                LDSM_X2(bl0, bl1, st + G_BL + brow + nb * (8 * TG) + ks * 32);
                MMA16816(sc[nb], ah, bh0, bh1);
                MMA16816(sc[nb], ah, bl0, bl1);
                MMA16816(sc[nb], al, bh0, bh1);
            }
        }
        __syncthreads();
    }

    const int r0 = bm + qr + g, r1 = r0 + 8;
    if (MODE == 1) {
#pragma unroll
        for (int nb = 0; nb < 8; nb++) {
            const int jj = bn + nb * 8 + tm * 2;
            const float b0 = bias[jj], b1 = bias[jj + 1];
            *(float2*)&out[(size_t)r0 * DIM + jj] = make_float2(sc[nb][0] + b0, sc[nb][1] + b1);
            *(float2*)&out[(size_t)r1 * DIM + jj] = make_float2(sc[nb][2] + b0, sc[nb][3] + b1);
        }
    } else {
        const int which = bn / DIM;
        const int head  = (bn % DIM) >> 6;
#pragma unroll
        for (int nb = 0; nb < 8; nb++) {
            const int jj  = bn + nb * 8 + tm * 2;
            const int col = nb * 8 + tm * 2;
            const float b0 = bias[jj], b1 = bias[jj + 1];
            float v00 = sc[nb][0] + b0, v01 = sc[nb][1] + b1;
            float v10 = sc[nb][2] + b0, v11 = sc[nb][3] + b1;
            if (which == 0) {
                *(uint32_t*)&g_Qf[((size_t)head * SLEN + r0) * HD + col] = packh2(v00, v01);
                *(uint32_t*)&g_Qf[((size_t)head * SLEN + r1) * HD + col] = packh2(v10, v11);
            } else if (which == 1) {
                *(uint32_t*)&g_Kf[((size_t)head * SLEN + r0) * HD + col] = packh2(v00, v01);
                *(uint32_t*)&g_Kf[((size_t)head * SLEN + r1) * HD + col] = packh2(v10, v11);
            } else {
                float vv[4] = {v00, v01, v10, v11};
                int rr[4] = {r0, r0, r1, r1};
                int cc[4] = {col, col + 1, col, col + 1};
#pragma unroll
                for (int e = 0; e < 4; e++)
                    g_Vt[((size_t)head * HD + cc[e]) * SLEN + rr[e]] = __float2half(vv[e]);
            }
        }
    }
}

// ---------------- rel-pos bias (Q from fp16) ---------------------------------
#define REL_SM_FLOATS (64 * 68 + 127 * 65)
__global__ void rel_kernel(const float* __restrict__ rph,
                           const float* __restrict__ rpw)
{
    extern __shared__ float sm[];
    float* Qs = sm;
    float* R  = sm + 64 * 68;
    const int qh = blockIdx.x, head = blockIdx.y;
    const int isW = blockIdx.z;
    const float* relpos = isW ? rpw : rph;
    const int tid = threadIdx.x;
    const int tx = tid & 15, ty = tid >> 4;

    const __half* Qg = &g_Qf[((size_t)head * SLEN + qh * GRD) * HD];
    for (int t = tid; t < 4096; t += 256) {
        int c = t & 63, qw = t >> 6;
        Qs[c * 68 + qw] = __half2float(Qg[(size_t)qw * HD + c]);
    }

    if (!isW) {
        for (int t = tid; t < 4096; t += 256) {
            int c = t & 63, kh = t >> 6;
            R[c * 68 + kh] = relpos[(qh - kh + 63) * 64 + c];
        }
        __syncthreads();
        float acc[4][4] = {};
#pragma unroll 4
        for (int c = 0; c < 64; c++) {
            float4 a = *(const float4*)&Qs[c * 68 + (ty << 2)];
            float4 b = *(const float4*)&R[c * 68 + (tx << 2)];
            float av[4] = {a.x, a.y, a.z, a.w};
            float bv[4] = {b.x, b.y, b.z, b.w};
#pragma unroll
            for (int i = 0; i < 4; i++)
#pragma unroll
                for (int j = 0; j < 4; j++) acc[i][j] += av[i] * bv[j];
        }
#pragma unroll
        for (int i = 0; i < 4; i++)
#pragma unroll
            for (int j = 0; j < 4; j++) {
                int qw = (ty << 2) + i, kh = (tx << 2) + j;
                g_relh[((size_t)head * SLEN + qh * 64 + qw) * 64 + kh] = acc[i][j];
            }
    } else {
        for (int t = tid; t < 127 * 64; t += 256) {
            int c = t & 63, rr = t >> 6;
            R[rr * 65 + c] = relpos[rr * 64 + c];
        }
        __syncthreads();
        float acc[4][4] = {};
        const int qwb = ty << 2, kwb = tx << 2;
        for (int c = 0; c < 64; c++) {
            float4 a = *(const float4*)&Qs[c * 68 + qwb];
            float av[4] = {a.x, a.y, a.z, a.w};
#pragma unroll
            for (int i = 0; i < 4; i++)
#pragma unroll
                for (int j = 0; j < 4; j++)
                    acc[i][j] += av[i] * R[(qwb + i - kwb - j + 63) * 65 + c];
        }
#pragma unroll
        for (int i = 0; i < 4; i++)
#pragma unroll
            for (int j = 0; j < 4; j++) {
                int qw = qwb + i, kw = kwb + j;
                g_relw[((size_t)head * SLEN + qh * 64 + qw) * 64 + kw] = acc[i][j];
            }
    }
}

// ---------------- fp16 single-pass flash attention ---------------------------
// 128 threads = 4 warps; q-tile 64; key-tile 64.  S = Q·K ; O += P·V.
// 64 MMAs per warp-tile (half of round 8).
#define TROW     144
#define KST(b)   ((b) * 9216)                 // K tile per stage
#define VST(b)   (18432 + (b) * 9216)         // V tile per stage
#define RH_OFF   36864
#define RW_OFF   (RH_OFF + 64 * 66 * 4)
#define SMEM_ATTN (RW_OFF + 64 * 66 * 4)      // 70656

__global__ void __launch_bounds__(128, 2) attn_mma_kernel()
{
    extern __shared__ char smem[];
    const uint32_t sb = smem_u32(smem);
    const int tid  = threadIdx.x;
    const int lane = tid & 31;
    const int warp = tid >> 5;
    const int g    = lane >> 2;
    const int tm   = lane & 3;
    const int head = blockIdx.y;
    const int q0   = blockIdx.x * 64;
    const int qr   = warp * 16;

    float* rhS = (float*)(smem + RH_OFF);
    float* rwS = (float*)(smem + RW_OFF);

    // rel tables pre-scaled by log2(e)
    for (int t = tid; t < 4096; t += 128) {
        int row = t >> 6, k = t & 63;
        rhS[row * 66 + k] = LOG2E * g_relh[((size_t)head * SLEN + q0 + row) * 64 + k];
        rwS[row * 66 + k] = LOG2E * g_relw[((size_t)head * SLEN + q0 + row) * 64 + k];
    }

    uint32_t qf[4][4];
    {
        const uint32_t* q0g = (const uint32_t*)(g_Qf + ((size_t)head * SLEN + q0 + qr + g) * HD);
        const uint32_t* q1g = (const uint32_t*)(g_Qf + ((size_t)head * SLEN + q0 + qr + g + 8) * HD);
#pragma unroll
        for (int ks = 0; ks < 4; ks++) {
            qf[ks][0] = q0g[ks * 8 + tm];     qf[ks][1] = q1g[ks * 8 + tm];
            qf[ks][2] = q0g[ks * 8 + tm + 4]; qf[ks][3] = q1g[ks * 8 + tm + 4];
        }
    }

    const uint32_t b4off = (uint32_t)((lane & 7) * TROW + ((lane >> 3) & 1) * 16 +
                                      ((lane >> 4) & 1) * (8 * TROW));

    const char* KG = (const char*)(g_Kf + (size_t)head * SLEN * HD);
    const char* VG = (const char*)(g_Vt + (size_t)head * HD * SLEN);

    auto load_tiles = [&](int buf, int kt) {
        const uint32_t kst = sb + KST(buf);
        const uint32_t vst = sb + VST(buf);
#pragma unroll
        for (int rep = 0; rep < 4; rep++) {
            int c = tid + rep * 128;
            int row = c >> 3, off = c & 7;
            CP_ASYNC16(kst + row * TROW + off * 16,
                       KG + (size_t)(kt * 64 + row) * 128 + off * 16);
            CP_ASYNC16(vst + row * TROW + off * 16,
                       VG + (size_t)row * 8192 + (size_t)kt * 128 + off * 16);
        }
    };

    float o[8][4];
#pragma unroll
    for (int cb = 0; cb < 8; cb++)
#pragma unroll
        for (int j = 0; j < 4; j++) o[cb][j] = 0.0f;
    float m0 = -1e30f, m1 = -1e30f, l0 = 0.0f, l1 = 0.0f;

    load_tiles(0, 0);
    CP_COMMIT();

    for (int kt = 0; kt < 64; kt++) {
        if (kt < 63) { load_tiles((kt + 1) & 1, kt + 1); CP_COMMIT(); CP_WAIT1(); }
        else         { CP_WAIT0(); }
        __syncthreads();

        const uint32_t kh0 = sb + KST(kt & 1) + b4off;

        // ---- S = Q · K  (single pass) ----
        float sc[8][4];
#pragma unroll
        for (int nb = 0; nb < 8; nb++)
#pragma unroll
            for (int j = 0; j < 4; j++) sc[nb][j] = 0.0f;

#pragma unroll
        for (int ks = 0; ks < 4; ks++) {
#pragma unroll
            for (int nb2 = 0; nb2 < 4; nb2++) {
                uint32_t b0, b1, b2, b3;
                LDSM_X4(b0, b1, b2, b3, kh0 + nb2 * (16 * TROW) + ks * 32);
                MMAH16816(sc[2 * nb2], qf[ks], b0, b1);
                MMAH16816(sc[2 * nb2 + 1], qf[ks], b2, b3);
            }
        }

        // ---- bias + online softmax (base-2; 0.125 folded in) ----
        const int r0 = qr + g, r1 = r0 + 8;
        const float rh0 = rhS[r0 * 66 + kt];
        const float rh1 = rhS[r1 * 66 + kt];
        float mt0 = -1e30f, mt1 = -1e30f;
#pragma unroll
        for (int nb = 0; nb < 8; nb++) {
            float2 w0 = *(const float2*)&rwS[r0 * 66 + nb * 8 + tm * 2];
            float2 w1 = *(const float2*)&rwS[r1 * 66 + nb * 8 + tm * 2];
            sc[nb][0] = fmaf(sc[nb][0], SCL2E, rh0 + w0.x);
            sc[nb][1] = fmaf(sc[nb][1], SCL2E, rh0 + w0.y);
            sc[nb][2] = fmaf(sc[nb][2], SCL2E, rh1 + w1.x);
            sc[nb][3] = fmaf(sc[nb][3], SCL2E, rh1 + w1.y);
            mt0 = fmaxf(mt0, fmaxf(sc[nb][0], sc[nb][1]));
            mt1 = fmaxf(mt1, fmaxf(sc[nb][2], sc[nb][3]));
        }
        mt0 = fmaxf(mt0, __shfl_xor_sync(0xffffffffu, mt0, 1));
        mt0 = fmaxf(mt0, __shfl_xor_sync(0xffffffffu, mt0, 2));
        mt1 = fmaxf(mt1, __shfl_xor_sync(0xffffffffu, mt1, 1));
        mt1 = fmaxf(mt1, __shfl_xor_sync(0xffffffffu, mt1, 2));

        const float mn0 = fmaxf(m0, mt0);
        const float mn1 = fmaxf(m1, mt1);
        const float a0 = exp2f(m0 - mn0);
        const float a1 = exp2f(m1 - mn1);
        m0 = mn0; m1 = mn1;

        float s0 = 0.0f, s1 = 0.0f;
#pragma unroll
        for (int nb = 0; nb < 8; nb++) {
            sc[nb][0] = exp2f(sc[nb][0] - mn0);
            sc[nb][1] = exp2f(sc[nb][1] - mn0);
            sc[nb][2] = exp2f(sc[nb][2] - mn1);
            sc[nb][3] = exp2f(sc[nb][3] - mn1);
            s0 += sc[nb][0] + sc[nb][1];
            s1 += sc[nb][2] + sc[nb][3];
        }
        s0 += __shfl_xor_sync(0xffffffffu, s0, 1);
        s0 += __shfl_xor_sync(0xffffffffu, s0, 2);
        s1 += __shfl_xor_sync(0xffffffffu, s1, 1);
        s1 += __shfl_xor_sync(0xffffffffu, s1, 2);
        l0 = l0 * a0 + s0;
        l1 = l1 * a1 + s1;

#pragma unroll
        for (int cb = 0; cb < 8; cb++) {
            o[cb][0] *= a0; o[cb][1] *= a0;
            o[cb][2] *= a1; o[cb][3] *= a1;
        }

        // ---- O += P · V  (single pass) ----
        const uint32_t vh0 = sb + VST(kt & 1) + b4off;
#pragma unroll
        for (int kb = 0; kb < 4; kb++) {
            uint32_t ph[4];
            ph[0] = packh2(sc[2 * kb][0],     sc[2 * kb][1]);
            ph[1] = packh2(sc[2 * kb][2],     sc[2 * kb][3]);
            ph[2] = packh2(sc[2 * kb + 1][0], sc[2 * kb + 1][1]);
            ph[3] = packh2(sc[2 * kb + 1][2], sc[2 * kb + 1][3]);
#pragma unroll
            for (int cb2 = 0; cb2 < 4; cb2++) {
                uint32_t h0, h1, h2, h3;
                LDSM_X4(h0, h1, h2, h3, vh0 + cb2 * (16 * TROW) + kb * 32);
                MMAH16816(o[2 * cb2], ph, h0, h1);
                MMAH16816(o[2 * cb2 + 1], ph, h2, h3);
            }
        }
        __syncthreads();
    }

    // ---- normalize + write split-bf16 attention output ----
    const float i0 = 1.0f / l0;
    const float i1 = 1.0f / l1;
    const size_t o0 = (size_t)(q0 + qr + g) * DIM + head * HD;
    const size_t o1 = (size_t)(q0 + qr + g + 8) * DIM + head * HD;
#pragma unroll
    for (int cb = 0; cb < 8; cb++) {
        const int col = cb * 8 + tm * 2;
        uint32_t h, l;
        split2(o[cb][0] * i0, o[cb][1] * i0, h, l);
        *(uint32_t*)&g_aoh[o0 + col] = h;
        *(uint32_t*)&g_aol[o0 + col] = l;
        split2(o[cb][2] * i1, o[cb][3] * i1, h, l);
        *(uint32_t*)&g_aoh[o1 + col] = h;
        *(uint32_t*)&g_aol[o1 + col] = l;
    }
}

// ---------------- launch ------------------------------------------------------
extern "C" void kernel_launch(void* const* d_in, const int* in_sizes, int n_in,
                              void* d_out, int out_size)
{
    const float* x      = (const float*)d_in[0];
    const float* qkv_w  = (const float*)d_in[1];
    const float* qkv_b  = (const float*)d_in[2];
    const float* proj_w = (const float*)d_in[3];
    const float* proj_b = (const float*)d_in[4];
    const float* rph    = (const float*)d_in[5];
    const float* rpw    = (const float*)d_in[6];
    float* out = (float*)d_out;

    const int rel_sm = REL_SM_FLOATS * (int)sizeof(float);
    cudaFuncSetAttribute(rel_kernel, cudaFuncAttributeMaxDynamicSharedMemorySize, rel_sm);
    cudaFuncSetAttribute(attn_mma_kernel, cudaFuncAttributeMaxDynamicSharedMemorySize, SMEM_ATTN);
    cudaFuncSetAttribute(gemm_bf16<0>, cudaFuncAttributeMaxDynamicSharedMemorySize, SMEM_GEMM);
    cudaFuncSetAttribute(gemm_bf16<1>, cudaFuncAttributeMaxDynamicSharedMemorySize, SMEM_GEMM);

    __nv_bfloat16 *Xh, *Xl, *W1h, *W1l, *W2h, *W2l, *AOh, *AOl;
    cudaGetSymbolAddress((void**)&Xh,  g_Xh);
    cudaGetSymbolAddress((void**)&Xl,  g_Xl);
    cudaGetSymbolAddress((void**)&W1h, g_W1h);
    cudaGetSymbolAddress((void**)&W1l, g_W1l);
    cudaGetSymbolAddress((void**)&W2h, g_W2h);
    cudaGetSymbolAddress((void**)&W2l, g_W2l);
    cudaGetSymbolAddress((void**)&AOh, g_aoh);
    cudaGetSymbolAddress((void**)&AOl, g_aol);

    // 1) split inputs to bf16 hi/lo
    convert_in<<<2048, 256>>>(x, qkv_w, proj_w);

    // 2) qkv GEMM (split bf16, fp32-grade) -> fp16 Q/K/V^T
    gemm_bf16<0><<<dim3(3 * DIM / 64, SLEN / 128), 256, SMEM_GEMM>>>(
        Xh, Xl, W1h, W1l, qkv_b, nullptr);

    // 3) rel-pos bias tables
    rel_kernel<<<dim3(GRD, NH, 2), 256, rel_sm>>>(rph, rpw);

    // 4) fp16 single-pass flash attention
    attn_mma_kernel<<<dim3(SLEN / 64, NH), 128, SMEM_ATTN>>>();

    // 5) proj GEMM (split bf16) -> out
    gemm_bf16<1><<<dim3(DIM / 64, SLEN / 128), 256, SMEM_GEMM>>>(
        AOh, AOl, W2h, W2l, proj_b, out);
}